// round 6
// baseline (speedup 1.0000x reference)
#include <cuda_runtime.h>
#include <cstdint>

// Problem dims
#define NS   512                 // B*S
#define DD   150
#define HH   64
#define GG   192                 // 3H
#define LTT  32
#define LCC  128
#define LSEQ 160                 // LTT + LCC
#define ROWS_T (NS*LTT)          // 16384
#define ROWS_ALL (NS*(LTT+LCC))  // 81920

// Scratch (device globals; no runtime alloc allowed)
__device__ float g_X [ROWS_ALL*DD];   // embed sums (layer0 input)
__device__ float g_xg[ROWS_ALL*GG];   // layer0 input projection (lane-interleaved cols)
__device__ float g_A [ROWS_ALL*HH];
__device__ float g_B [ROWS_ALL*HH];

// ---------- f32x2 helpers ----------
__device__ __forceinline__ unsigned long long pk2(float a, float b){
    unsigned long long r; asm("mov.b64 %0,{%1,%2};" : "=l"(r) : "f"(a), "f"(b)); return r;
}
__device__ __forceinline__ void fma2(unsigned long long &acc, unsigned long long a, unsigned long long b){
    asm("fma.rn.f32x2 %0, %1, %2, %0;" : "+l"(acc) : "l"(a), "l"(b));
}
__device__ __forceinline__ float upk_sum(unsigned long long a){
    float x, y; asm("mov.b64 {%0,%1}, %2;" : "=f"(x), "=f"(y) : "l"(a)); return x + y;
}

__device__ __forceinline__ float sigmoidf_(float x){
    return __fdividef(1.f, 1.f + __expf(-x));
}
__device__ __forceinline__ float tanhf_(float x){
    float ax = fabsf(x);
    float e  = __expf(-2.f*ax);
    float t  = __fdividef(1.f - e, 1.f + e);
    return (x < 0.f) ? -t : t;
}

// ---------- 1) embedding-bag sums ----------
__global__ void embed_kernel(const int* __restrict__ titles,
                             const int* __restrict__ contents,
                             const float* __restrict__ emb)
{
    int idx = blockIdx.x*blockDim.x + threadIdx.x;
    if (idx >= ROWS_ALL*75) return;          // 75 float2 per row (D=150)
    int row = idx / 75;
    int dp  = idx - row*75;

    const int* ip; int stride;
    if (row < ROWS_T){ int n = row >> 5, t = row & 31;  ip = titles   + (n*6)*32  + t; stride = 32; }
    else             { int r = row - ROWS_T;
                       int n = r >> 7,   t = r & 127;   ip = contents + (n*6)*128 + t; stride = 128; }

    float ax = 0.f, ay = 0.f;
    #pragma unroll
    for (int i = 0; i < 6; i++){
        int ix = ip[i*stride];
        if (ix != 0){
            float2 v = *(const float2*)(emb + (size_t)ix*DD + 2*dp);
            ax += v.x; ay += v.y;
        }
    }
    *(float2*)(g_X + (size_t)row*DD + 2*dp) = make_float2(ax, ay);
}

// ---------- 2) layer-0 input projection GEMM (K=150) ----------
// Stores columns in lane-interleaved order: gate g=(role*64+i) -> position 3*i+role.
__global__ void __launch_bounds__(256) xg_gemm150(const float* __restrict__ W,
                                                  const float* __restrict__ bias)
{
    __shared__ float sw[30*194];
    __shared__ float sx[64*32];
    int tid = threadIdx.x;
    int tx = tid & 31, ty = tid >> 5;
    int r0 = blockIdx.x * 64;

    unsigned long long acc[8][3];
    #pragma unroll
    for (int r = 0; r < 8; r++)
        #pragma unroll
        for (int c = 0; c < 3; c++) acc[r][c] = 0ull;

    for (int k0 = 0; k0 < 150; k0 += 30){
        for (int i = tid; i < 30*192; i += 256){
            int gg = i/30, kk = i - gg*30;
            sw[kk*194 + gg] = W[gg*150 + k0 + kk];
        }
        for (int i = tid; i < 64*30; i += 256){
            int rr = i/30, kk = i - rr*30;
            sx[rr*32 + kk] = g_X[(size_t)(r0+rr)*150 + k0 + kk];
        }
        __syncthreads();
        #pragma unroll 6
        for (int kk = 0; kk < 30; kk++){
            unsigned long long w2[3];
            #pragma unroll
            for (int c = 0; c < 3; c++)
                w2[c] = *(const unsigned long long*)&sw[kk*194 + tx*6 + 2*c];
            #pragma unroll
            for (int r = 0; r < 8; r++){
                float xv = sx[(ty*8 + r)*32 + kk];
                unsigned long long x2 = pk2(xv, xv);
                #pragma unroll
                for (int c = 0; c < 3; c++) fma2(acc[r][c], w2[c], x2);
            }
        }
        __syncthreads();
    }
    #pragma unroll
    for (int r = 0; r < 8; r++){
        int row = r0 + ty*8 + r;
        #pragma unroll
        for (int c = 0; c < 3; c++){
            float lo, hi;
            asm("mov.b64 {%0,%1}, %2;" : "=f"(lo), "=f"(hi) : "l"(acc[r][c]));
            int g0 = tx*6 + 2*c;
            int p0 = 3*(g0 & 63) + (g0 >> 6);          // interleaved position
            int g1 = g0 + 1;
            int p1 = 3*(g1 & 63) + (g1 >> 6);
            g_xg[(size_t)row*GG + p0] = lo + bias[g0];
            g_xg[(size_t)row*GG + p1] = hi + bias[g1];
        }
    }
}

// ---------- 3) GRU recurrence: lane-triple gates, ONE barrier per step ----------
// 224 threads = 7 warps. Lane triple (3k,3k+1,3k+2) of warp w owns element
// i = 10*w + k: roles r,z,n. Each thread holds its gate row (Whh row, + Wih row
// if FUSED) in registers. r/z lanes do their sigmoid; n lane gets r,z via shfl,
// computes tanh + h-update, publishes h. One __syncthreads per step.
// mode 0: info mid (X layout), mode 1: info final (X in, concat out),
// mode 2: comb (concat, T=160). Info modes run 2 segments (content then title).
template<bool FUSED, int NSEQ>
__global__ void __launch_bounds__(224) gru_rec(
    const float* __restrict__ xin,
    const float* __restrict__ Wih, const float* __restrict__ bih,
    const float* __restrict__ Whh, const float* __restrict__ bhh,
    float* __restrict__ yout, float* __restrict__ hid,
    int mode, int layer)
{
    __shared__ __align__(16) float sh_h[2][NSEQ][64];
    __shared__ __align__(16) float sh_x[FUSED ? 2 : 1][NSEQ][64];

    const int tid  = threadIdx.x;
    const int w    = tid >> 5, l = tid & 31;
    const int kk   = w*10 + l/3;
    const int role = l % 3;
    const bool valid = (l < 30) && (kk < 64);
    const int elem = valid ? kk : 0;
    const int row  = role*64 + elem;              // gate row this thread owns
    const int col  = (w*30 + l < GG) ? (w*30 + l) : (GG-1);  // interleaved xg col

    // weight rows -> registers
    unsigned long long wh[32];
    {   const float2* p = (const float2*)(Whh + row*HH);
        #pragma unroll
        for (int j = 0; j < 32; j++){ float2 v = __ldg(p + j); wh[j] = pk2(v.x, v.y); }
    }
    unsigned long long wx[FUSED ? 32 : 1];
    float bx_ = 0.f;
    if (FUSED){
        const float2* p = (const float2*)(Wih + row*HH);
        #pragma unroll
        for (int j = 0; j < 32; j++){ float2 v = __ldg(p + j); wx[j] = pk2(v.x, v.y); }
        bx_ = bih[row];
    }
    const float bh_ = bhh[row];

    const int n0 = blockIdx.x * NSEQ;
    const int NSEG = (mode == 2) ? 1 : 2;

    for (int seg = 0; seg < NSEG; seg++){
        int T;
        int ibase[NSEQ], ob[NSEQ];
        if (mode == 2){
            T = LSEQ;
            #pragma unroll
            for (int s = 0; s < NSEQ; s++){ ibase[s] = (n0+s)*LSEQ; ob[s] = ibase[s]; }
        } else if (seg == 0){   // content
            T = LCC;
            #pragma unroll
            for (int s = 0; s < NSEQ; s++){
                ibase[s] = ROWS_T + (n0+s)*LCC;
                ob[s] = (mode == 1) ? (n0+s)*LSEQ + LTT : ibase[s];
            }
        } else {                // titles
            T = LTT;
            #pragma unroll
            for (int s = 0; s < NSEQ; s++){
                ibase[s] = (n0+s)*LTT;
                ob[s] = (mode == 1) ? (n0+s)*LSEQ : ibase[s];
            }
        }

        // zero h
        for (int idx = tid; idx < NSEQ*64; idx += 224)
            sh_h[0][idx >> 6][idx & 63] = 0.f;

        // prime x pipeline
        float xr [FUSED ? NSEQ : 1];
        float axc[FUSED ? 1 : NSEQ];
        if (FUSED){
            if (role == 1 && valid){
                #pragma unroll
                for (int s = 0; s < NSEQ; s++){
                    sh_x[0][s][elem] = __ldg(xin + (size_t)ibase[s]*HH + elem);
                    xr[s] = __ldg(xin + (size_t)(ibase[s]+1)*HH + elem);
                }
            }
        } else {
            #pragma unroll
            for (int s = 0; s < NSEQ; s++)
                axc[s] = __ldg(xin + (size_t)ibase[s]*GG + col);
        }
        __syncthreads();

        int p = 0;
        for (int t = 0; t < T; t++){
            // non-fused: prefetch next xg early
            float axn[FUSED ? 1 : NSEQ];
            if (!FUSED){
                #pragma unroll
                for (int s = 0; s < NSEQ; s++)
                    axn[s] = (t+1 < T) ? __ldg(xin + (size_t)(ibase[s]+t+1)*GG + col) : 0.f;
            }

            // matvecs
            unsigned long long accH[NSEQ];
            unsigned long long accX[FUSED ? NSEQ : 1];
            #pragma unroll
            for (int s = 0; s < NSEQ; s++){ accH[s] = 0ull; if (FUSED) accX[s] = 0ull; }
            #pragma unroll
            for (int j = 0; j < 16; j++){
                #pragma unroll
                for (int s = 0; s < NSEQ; s++){
                    ulonglong2 h4 = ((const ulonglong2*)sh_h[p][s])[j];
                    fma2(accH[s], wh[2*j],   h4.x);
                    fma2(accH[s], wh[2*j+1], h4.y);
                    if (FUSED){
                        ulonglong2 x4 = ((const ulonglong2*)sh_x[p][s])[j];
                        fma2(accX[s], wx[2*j],   x4.x);
                        fma2(accX[s], wx[2*j+1], x4.y);
                    }
                }
            }

            float v[NSEQ], ax_[NSEQ], ah_[NSEQ];
            #pragma unroll
            for (int s = 0; s < NSEQ; s++){
                ah_[s] = bh_ + upk_sum(accH[s]);
                ax_[s] = FUSED ? (bx_ + upk_sum(accX[s])) : axc[s];
                v[s]   = sigmoidf_(ax_[s] + ah_[s]);      // meaningful for r/z lanes
            }

            // z-lanes: stage x(t+1), refill xr with x(t+2)
            if (FUSED && role == 1 && valid){
                if (t+1 < T){
                    #pragma unroll
                    for (int s = 0; s < NSEQ; s++) sh_x[p^1][s][elem] = xr[s];
                }
                if (t+2 < T){
                    #pragma unroll
                    for (int s = 0; s < NSEQ; s++)
                        xr[s] = __ldg(xin + (size_t)(ibase[s]+t+2)*HH + elem);
                }
            }

            // shuffle-exchange + h update (n-lanes)
            #pragma unroll
            for (int s = 0; s < NSEQ; s++){
                float rv = __shfl_sync(0xFFFFFFFFu, v[s], (l+30) & 31);   // lane l-2
                float zv = __shfl_sync(0xFFFFFFFFu, v[s], (l+31) & 31);   // lane l-1
                float nn = tanhf_(ax_[s] + rv*ah_[s]);
                float hold = sh_h[p][s][elem];
                float hnew = zv*(hold - nn) + nn;
                if (role == 2 && valid){
                    sh_h[p^1][s][elem] = hnew;
                    yout[(size_t)(ob[s] + t)*HH + elem] = hnew;
                }
            }
            __syncthreads();
            if (!FUSED){
                #pragma unroll
                for (int s = 0; s < NSEQ; s++) axc[s] = axn[s];
            }
            p ^= 1;
        }

        if (mode == 2 && hid != nullptr && role == 2 && valid){
            #pragma unroll
            for (int s = 0; s < NSEQ; s++){
                int n = n0 + s;
                int bi = n >> 6, sidx = n & 63;
                hid[(size_t)(((bi*4 + layer)*64 + sidx)*64) + elem] = sh_h[p][s][elem];
            }
        }
        if (seg + 1 < NSEG) __syncthreads();
    }
}

// ---------- 4) prices passthrough ----------
__global__ void tail_kernel(const float* __restrict__ prices, float* __restrict__ out){
    int i = threadIdx.x;
    if (i < 512) out[i] = prices[i];
}

extern "C" void kernel_launch(void* const* d_in, const int* in_sizes, int n_in,
                              void* d_out, int out_size)
{
    const int*   titles   = (const int*)  d_in[0];
    const int*   contents = (const int*)  d_in[1];
    const float* prices   = (const float*)d_in[2];
    const float* emb      = (const float*)d_in[3];
    const float* iWih0    = (const float*)d_in[4];
    const float* iWhh0    = (const float*)d_in[5];
    const float* ibih0    = (const float*)d_in[6];
    const float* ibhh0    = (const float*)d_in[7];
    const float* iWih     = (const float*)d_in[8];   // [3][192][64]
    const float* iWhh     = (const float*)d_in[9];
    const float* ibih     = (const float*)d_in[10];  // [3][192]
    const float* ibhh     = (const float*)d_in[11];
    const float* cWih     = (const float*)d_in[12];  // [4][192][64]
    const float* cWhh     = (const float*)d_in[13];
    const float* cbih     = (const float*)d_in[14];
    const float* cbhh     = (const float*)d_in[15];

    float* out = (float*)d_out;
    float* hid = out + (size_t)8*64*160*64;          // encoder_hidden region
    float* pr  = hid + (size_t)8*4*64*64;            // prices region

    float *pXG = nullptr, *pA = nullptr, *pB = nullptr;
    cudaGetSymbolAddress((void**)&pXG, g_xg);
    cudaGetSymbolAddress((void**)&pA,  g_A);
    cudaGetSymbolAddress((void**)&pB,  g_B);

    // 1) embedding bags
    embed_kernel<<<(ROWS_ALL*75 + 255)/256, 256>>>(titles, contents, emb);

    // 2) info layer 0: projection GEMM (interleaved store) then recurrence
    xg_gemm150<<<ROWS_ALL/64, 256>>>(iWih0, ibih0);
    gru_rec<false,4><<<128, 224>>>(pXG, nullptr, nullptr, iWhh0, ibhh0, pA, nullptr, 0, 0);

    // info layers 1..3 (fused); layer 3 writes concat layout
    gru_rec<true,4><<<128, 224>>>(pA, iWih + 0*GG*HH, ibih + 0*GG,
                                  iWhh + 0*GG*HH, ibhh + 0*GG, pB, nullptr, 0, 0);
    gru_rec<true,4><<<128, 224>>>(pB, iWih + 1*GG*HH, ibih + 1*GG,
                                  iWhh + 1*GG*HH, ibhh + 1*GG, pA, nullptr, 0, 0);
    gru_rec<true,4><<<128, 224>>>(pA, iWih + 2*GG*HH, ibih + 2*GG,
                                  iWhh + 2*GG*HH, ibhh + 2*GG, pB, nullptr, 1, 0);

    // comb layers 0..3 (T=160); final layer writes encoder_outputs
    gru_rec<true,4><<<128, 224>>>(pB, cWih + 0*GG*HH, cbih + 0*GG,
                                  cWhh + 0*GG*HH, cbhh + 0*GG, pA,  hid, 2, 0);
    gru_rec<true,4><<<128, 224>>>(pA, cWih + 1*GG*HH, cbih + 1*GG,
                                  cWhh + 1*GG*HH, cbhh + 1*GG, pB,  hid, 2, 1);
    gru_rec<true,4><<<128, 224>>>(pB, cWih + 2*GG*HH, cbih + 2*GG,
                                  cWhh + 2*GG*HH, cbhh + 2*GG, pA,  hid, 2, 2);
    gru_rec<true,4><<<128, 224>>>(pA, cWih + 3*GG*HH, cbih + 3*GG,
                                  cWhh + 3*GG*HH, cbhh + 3*GG, out, hid, 2, 3);

    // prices passthrough
    tail_kernel<<<1, 512>>>(prices, pr);
}

// round 7
// speedup vs baseline: 1.1722x; 1.1722x over previous
#include <cuda_runtime.h>
#include <cstdint>

// Problem dims
#define NS   512                 // B*S
#define DD   150
#define HH   64
#define GG   192                 // 3H
#define LTT  32
#define LCC  128
#define LSEQ 160                 // LTT + LCC
#define ROWS_T (NS*LTT)          // 16384
#define ROWS_ALL (NS*(LTT+LCC))  // 81920

// Scratch (device globals; no runtime alloc allowed)
__device__ float g_X [ROWS_ALL*DD];   // embed sums (layer0 input)
__device__ float g_xg[ROWS_ALL*GG];   // per-layer input projection (interleaved cols)
__device__ float g_A [ROWS_ALL*HH];
__device__ float g_B [ROWS_ALL*HH];

// ---------- f32x2 helpers ----------
__device__ __forceinline__ unsigned long long pk2(float a, float b){
    unsigned long long r; asm("mov.b64 %0,{%1,%2};" : "=l"(r) : "f"(a), "f"(b)); return r;
}
__device__ __forceinline__ void fma2(unsigned long long &acc, unsigned long long a, unsigned long long b){
    asm("fma.rn.f32x2 %0, %1, %2, %0;" : "+l"(acc) : "l"(a), "l"(b));
}
__device__ __forceinline__ float upk_sum(unsigned long long a){
    float x, y; asm("mov.b64 {%0,%1}, %2;" : "=f"(x), "=f"(y) : "l"(a)); return x + y;
}

__device__ __forceinline__ float sigmoidf_(float x){
    return __fdividef(1.f, 1.f + __expf(-x));
}
__device__ __forceinline__ float tanhf_(float x){
    float ax = fabsf(x);
    float e  = __expf(-2.f*ax);
    float t  = __fdividef(1.f - e, 1.f + e);
    return (x < 0.f) ? -t : t;
}

// interleaved column position for gate row g = role*64 + elem  ->  3*elem + role
__device__ __forceinline__ int ilv(int g){ return 3*(g & 63) + (g >> 6); }

// ---------- 1) embedding-bag sums ----------
__global__ void embed_kernel(const int* __restrict__ titles,
                             const int* __restrict__ contents,
                             const float* __restrict__ emb)
{
    int idx = blockIdx.x*blockDim.x + threadIdx.x;
    if (idx >= ROWS_ALL*75) return;          // 75 float2 per row (D=150)
    int row = idx / 75;
    int dp  = idx - row*75;

    const int* ip; int stride;
    if (row < ROWS_T){ int n = row >> 5, t = row & 31;  ip = titles   + (n*6)*32  + t; stride = 32; }
    else             { int r = row - ROWS_T;
                       int n = r >> 7,   t = r & 127;   ip = contents + (n*6)*128 + t; stride = 128; }

    float ax = 0.f, ay = 0.f;
    #pragma unroll
    for (int i = 0; i < 6; i++){
        int ix = ip[i*stride];
        if (ix != 0){
            float2 v = *(const float2*)(emb + (size_t)ix*DD + 2*dp);
            ax += v.x; ay += v.y;
        }
    }
    *(float2*)(g_X + (size_t)row*DD + 2*dp) = make_float2(ax, ay);
}

// ---------- 2a) layer-0 input projection GEMM (K=150), interleaved store ----------
__global__ void __launch_bounds__(256) xg_gemm150(const float* __restrict__ W,
                                                  const float* __restrict__ bias)
{
    __shared__ float sw[30*194];
    __shared__ float sx[64*32];
    int tid = threadIdx.x;
    int tx = tid & 31, ty = tid >> 5;
    int r0 = blockIdx.x * 64;

    unsigned long long acc[8][3];
    #pragma unroll
    for (int r = 0; r < 8; r++)
        #pragma unroll
        for (int c = 0; c < 3; c++) acc[r][c] = 0ull;

    for (int k0 = 0; k0 < 150; k0 += 30){
        for (int i = tid; i < 30*192; i += 256){
            int gg = i/30, kk = i - gg*30;
            sw[kk*194 + gg] = W[gg*150 + k0 + kk];
        }
        for (int i = tid; i < 64*30; i += 256){
            int rr = i/30, kk = i - rr*30;
            sx[rr*32 + kk] = g_X[(size_t)(r0+rr)*150 + k0 + kk];
        }
        __syncthreads();
        #pragma unroll 6
        for (int kk = 0; kk < 30; kk++){
            unsigned long long w2[3];
            #pragma unroll
            for (int c = 0; c < 3; c++)
                w2[c] = *(const unsigned long long*)&sw[kk*194 + tx*6 + 2*c];
            #pragma unroll
            for (int r = 0; r < 8; r++){
                float xv = sx[(ty*8 + r)*32 + kk];
                unsigned long long x2 = pk2(xv, xv);
                #pragma unroll
                for (int c = 0; c < 3; c++) fma2(acc[r][c], w2[c], x2);
            }
        }
        __syncthreads();
    }
    #pragma unroll
    for (int r = 0; r < 8; r++){
        int row = r0 + ty*8 + r;
        #pragma unroll
        for (int c = 0; c < 3; c++){
            float lo, hi;
            asm("mov.b64 {%0,%1}, %2;" : "=f"(lo), "=f"(hi) : "l"(acc[r][c]));
            int g0 = tx*6 + 2*c;
            g_xg[(size_t)row*GG + ilv(g0)]   = lo + bias[g0];
            g_xg[(size_t)row*GG + ilv(g0+1)] = hi + bias[g0+1];
        }
    }
}

// ---------- 2b) K=64 input projection GEMM (layers 1+), interleaved store ----------
__global__ void __launch_bounds__(256) xg_gemm64(const float* __restrict__ X,
                                                 const float* __restrict__ W,
                                                 const float* __restrict__ bias)
{
    __shared__ float sw[32*194];
    __shared__ float sx[64*33];
    int tid = threadIdx.x;
    int tx = tid & 31, ty = tid >> 5;
    int r0 = blockIdx.x * 64;

    unsigned long long acc[8][3];
    #pragma unroll
    for (int r = 0; r < 8; r++)
        #pragma unroll
        for (int c = 0; c < 3; c++) acc[r][c] = 0ull;

    #pragma unroll
    for (int k0 = 0; k0 < 64; k0 += 32){
        for (int i = tid; i < 32*192; i += 256){
            int gg = i >> 5, kk = i & 31;
            sw[kk*194 + gg] = W[gg*64 + k0 + kk];
        }
        for (int i = tid; i < 64*32; i += 256){
            int rr = i >> 5, kk = i & 31;
            sx[rr*33 + kk] = X[(size_t)(r0+rr)*64 + k0 + kk];
        }
        __syncthreads();
        #pragma unroll 8
        for (int kk = 0; kk < 32; kk++){
            unsigned long long w2[3];
            #pragma unroll
            for (int c = 0; c < 3; c++)
                w2[c] = *(const unsigned long long*)&sw[kk*194 + tx*6 + 2*c];
            #pragma unroll
            for (int r = 0; r < 8; r++){
                float xv = sx[(ty*8 + r)*33 + kk];
                unsigned long long x2 = pk2(xv, xv);
                #pragma unroll
                for (int c = 0; c < 3; c++) fma2(acc[r][c], w2[c], x2);
            }
        }
        __syncthreads();
    }
    #pragma unroll
    for (int r = 0; r < 8; r++){
        int row = r0 + ty*8 + r;
        #pragma unroll
        for (int c = 0; c < 3; c++){
            float lo, hi;
            asm("mov.b64 {%0,%1}, %2;" : "=f"(lo), "=f"(hi) : "l"(acc[r][c]));
            int g0 = tx*6 + 2*c;
            g_xg[(size_t)row*GG + ilv(g0)]   = lo + bias[g0];
            g_xg[(size_t)row*GG + ilv(g0+1)] = hi + bias[g0+1];
        }
    }
}

// ---------- 3) GRU recurrence: h-matvec only, lane-triple gates, 1 barrier/step ----------
// 224 threads = 7 warps; lane triple (3k,3k+1,3k+2) of warp w owns element
// i = 10*w + k with roles r,z,n. Thread holds only its Whh row (64 regs) ->
// 2 CTAs/SM. xg read from gmem with distance-1 prefetch.
// mode 0: info mid (X layout), mode 1: info final (X in, concat out),
// mode 2: comb (concat, T=160). Info modes: content segment then title segment.
template<int NSEQ>
__global__ void __launch_bounds__(224, 2) gru_rec(
    const float* __restrict__ xg,
    const float* __restrict__ Whh, const float* __restrict__ bhh,
    float* __restrict__ yout, float* __restrict__ hid,
    int mode, int layer)
{
    __shared__ __align__(16) float sh_h[2][NSEQ][64];

    const int tid  = threadIdx.x;
    const int w    = tid >> 5, l = tid & 31;
    const int kk   = w*10 + l/3;
    const int role = l % 3;
    const bool valid = (l < 30) && (kk < 64);
    const int elem = valid ? kk : 0;
    const int row  = role*64 + elem;                         // gate row owned
    const int col  = (w*30 + l < GG) ? (w*30 + l) : (GG-1);  // interleaved xg col

    unsigned long long wh[32];
    {   const float2* p = (const float2*)(Whh + row*HH);
        #pragma unroll
        for (int j = 0; j < 32; j++){ float2 v = __ldg(p + j); wh[j] = pk2(v.x, v.y); }
    }
    const float bh_ = bhh[row];

    const int n0 = blockIdx.x * NSEQ;
    const int NSEG = (mode == 2) ? 1 : 2;

    for (int seg = 0; seg < NSEG; seg++){
        int T;
        int ibase[NSEQ], ob[NSEQ];
        if (mode == 2){
            T = LSEQ;
            #pragma unroll
            for (int s = 0; s < NSEQ; s++){ ibase[s] = (n0+s)*LSEQ; ob[s] = ibase[s]; }
        } else if (seg == 0){   // content
            T = LCC;
            #pragma unroll
            for (int s = 0; s < NSEQ; s++){
                ibase[s] = ROWS_T + (n0+s)*LCC;
                ob[s] = (mode == 1) ? (n0+s)*LSEQ + LTT : ibase[s];
            }
        } else {                // titles
            T = LTT;
            #pragma unroll
            for (int s = 0; s < NSEQ; s++){
                ibase[s] = (n0+s)*LTT;
                ob[s] = (mode == 1) ? (n0+s)*LSEQ : ibase[s];
            }
        }

        for (int idx = tid; idx < NSEQ*64; idx += 224)
            sh_h[0][idx >> 6][idx & 63] = 0.f;

        float axc[NSEQ];
        #pragma unroll
        for (int s = 0; s < NSEQ; s++)
            axc[s] = __ldg(xg + (size_t)ibase[s]*GG + col);
        __syncthreads();

        int p = 0;
        for (int t = 0; t < T; t++){
            // prefetch next step's xg early
            float axn[NSEQ];
            #pragma unroll
            for (int s = 0; s < NSEQ; s++)
                axn[s] = (t+1 < T) ? __ldg(xg + (size_t)(ibase[s]+t+1)*GG + col) : 0.f;

            // h-matvec
            unsigned long long accH[NSEQ];
            #pragma unroll
            for (int s = 0; s < NSEQ; s++) accH[s] = 0ull;
            #pragma unroll
            for (int j = 0; j < 16; j++){
                #pragma unroll
                for (int s = 0; s < NSEQ; s++){
                    ulonglong2 h4 = ((const ulonglong2*)sh_h[p][s])[j];
                    fma2(accH[s], wh[2*j],   h4.x);
                    fma2(accH[s], wh[2*j+1], h4.y);
                }
            }

            float v[NSEQ], ax_[NSEQ], ah_[NSEQ];
            #pragma unroll
            for (int s = 0; s < NSEQ; s++){
                ah_[s] = bh_ + upk_sum(accH[s]);
                ax_[s] = axc[s];
                v[s]   = sigmoidf_(ax_[s] + ah_[s]);     // meaningful for r/z lanes
            }

            // n-lanes gather r,z via shfl; compute tanh + h update
            #pragma unroll
            for (int s = 0; s < NSEQ; s++){
                float rv = __shfl_sync(0xFFFFFFFFu, v[s], (l+30) & 31);   // lane l-2
                float zv = __shfl_sync(0xFFFFFFFFu, v[s], (l+31) & 31);   // lane l-1
                float nn = tanhf_(ax_[s] + rv*ah_[s]);
                float hold = sh_h[p][s][elem];
                float hnew = zv*(hold - nn) + nn;
                if (role == 2 && valid){
                    sh_h[p^1][s][elem] = hnew;
                    yout[(size_t)(ob[s] + t)*HH + elem] = hnew;
                }
            }
            __syncthreads();
            #pragma unroll
            for (int s = 0; s < NSEQ; s++) axc[s] = axn[s];
            p ^= 1;
        }

        if (mode == 2 && hid != nullptr && role == 2 && valid){
            #pragma unroll
            for (int s = 0; s < NSEQ; s++){
                int n = n0 + s;
                int bi = n >> 6, sidx = n & 63;
                hid[(size_t)(((bi*4 + layer)*64 + sidx)*64) + elem] = sh_h[p][s][elem];
            }
        }
        if (seg + 1 < NSEG) __syncthreads();
    }
}

// ---------- 4) prices passthrough ----------
__global__ void tail_kernel(const float* __restrict__ prices, float* __restrict__ out){
    int i = threadIdx.x;
    if (i < 512) out[i] = prices[i];
}

extern "C" void kernel_launch(void* const* d_in, const int* in_sizes, int n_in,
                              void* d_out, int out_size)
{
    const int*   titles   = (const int*)  d_in[0];
    const int*   contents = (const int*)  d_in[1];
    const float* prices   = (const float*)d_in[2];
    const float* emb      = (const float*)d_in[3];
    const float* iWih0    = (const float*)d_in[4];
    const float* iWhh0    = (const float*)d_in[5];
    const float* ibih0    = (const float*)d_in[6];
    const float* ibhh0    = (const float*)d_in[7];
    const float* iWih     = (const float*)d_in[8];   // [3][192][64]
    const float* iWhh     = (const float*)d_in[9];
    const float* ibih     = (const float*)d_in[10];  // [3][192]
    const float* ibhh     = (const float*)d_in[11];
    const float* cWih     = (const float*)d_in[12];  // [4][192][64]
    const float* cWhh     = (const float*)d_in[13];
    const float* cbih     = (const float*)d_in[14];
    const float* cbhh     = (const float*)d_in[15];

    float* out = (float*)d_out;
    float* hid = out + (size_t)8*64*160*64;          // encoder_hidden region
    float* pr  = hid + (size_t)8*4*64*64;            // prices region

    float *pXG = nullptr, *pA = nullptr, *pB = nullptr;
    cudaGetSymbolAddress((void**)&pXG, g_xg);
    cudaGetSymbolAddress((void**)&pA,  g_A);
    cudaGetSymbolAddress((void**)&pB,  g_B);

    const int GRID_G = ROWS_ALL/64;   // 1280

    // 1) embedding bags
    embed_kernel<<<(ROWS_ALL*75 + 255)/256, 256>>>(titles, contents, emb);

    // info layer 0
    xg_gemm150<<<GRID_G, 256>>>(iWih0, ibih0);
    gru_rec<2><<<256, 224>>>(pXG, iWhh0, ibhh0, pA, nullptr, 0, 0);

    // info layers 1..3; layer 3 writes concat layout
    xg_gemm64<<<GRID_G, 256>>>(pA, iWih + 0*GG*HH, ibih + 0*GG);
    gru_rec<2><<<256, 224>>>(pXG, iWhh + 0*GG*HH, ibhh + 0*GG, pB, nullptr, 0, 0);

    xg_gemm64<<<GRID_G, 256>>>(pB, iWih + 1*GG*HH, ibih + 1*GG);
    gru_rec<2><<<256, 224>>>(pXG, iWhh + 1*GG*HH, ibhh + 1*GG, pA, nullptr, 0, 0);

    xg_gemm64<<<GRID_G, 256>>>(pA, iWih + 2*GG*HH, ibih + 2*GG);
    gru_rec<2><<<256, 224>>>(pXG, iWhh + 2*GG*HH, ibhh + 2*GG, pB, nullptr, 1, 0);

    // comb layers 0..3 (concat layout, T=160); final layer writes encoder_outputs
    xg_gemm64<<<GRID_G, 256>>>(pB, cWih + 0*GG*HH, cbih + 0*GG);
    gru_rec<2><<<256, 224>>>(pXG, cWhh + 0*GG*HH, cbhh + 0*GG, pA,  hid, 2, 0);

    xg_gemm64<<<GRID_G, 256>>>(pA, cWih + 1*GG*HH, cbih + 1*GG);
    gru_rec<2><<<256, 224>>>(pXG, cWhh + 1*GG*HH, cbhh + 1*GG, pB,  hid, 2, 1);

    xg_gemm64<<<GRID_G, 256>>>(pB, cWih + 2*GG*HH, cbih + 2*GG);
    gru_rec<2><<<256, 224>>>(pXG, cWhh + 2*GG*HH, cbhh + 2*GG, pA,  hid, 2, 2);

    xg_gemm64<<<GRID_G, 256>>>(pA, cWih + 3*GG*HH, cbih + 3*GG);
    gru_rec<2><<<256, 224>>>(pXG, cWhh + 3*GG*HH, cbhh + 3*GG, out, hid, 2, 3);

    // prices passthrough
    tail_kernel<<<1, 512>>>(prices, pr);
}

// round 8
// speedup vs baseline: 1.1852x; 1.0111x over previous
#include <cuda_runtime.h>
#include <cstdint>

// Problem dims
#define NS   512                 // B*S
#define DD   150
#define HH   64
#define GG   192                 // 3H
#define LTT  32
#define LCC  128
#define LSEQ 160                 // LTT + LCC
#define ROWS_T (NS*LTT)          // 16384
#define ROWS_ALL (NS*(LTT+LCC))  // 81920

// Scratch (device globals; no runtime alloc allowed)
__device__ float g_X [ROWS_ALL*DD];   // embed sums (layer0 input)
__device__ float g_xg[ROWS_ALL*GG];   // per-layer input projection (interleaved cols)
__device__ float g_A [ROWS_ALL*HH];
__device__ float g_B [ROWS_ALL*HH];

// ---------- f32x2 helpers ----------
__device__ __forceinline__ unsigned long long pk2(float a, float b){
    unsigned long long r; asm("mov.b64 %0,{%1,%2};" : "=l"(r) : "f"(a), "f"(b)); return r;
}
__device__ __forceinline__ void fma2(unsigned long long &acc, unsigned long long a, unsigned long long b){
    asm("fma.rn.f32x2 %0, %1, %2, %0;" : "+l"(acc) : "l"(a), "l"(b));
}
__device__ __forceinline__ float upk_sum(unsigned long long a){
    float x, y; asm("mov.b64 {%0,%1}, %2;" : "=f"(x), "=f"(y) : "l"(a)); return x + y;
}

__device__ __forceinline__ float sigmoidf_(float x){
    return __fdividef(1.f, 1.f + __expf(-x));
}
__device__ __forceinline__ float tanhf_(float x){
    float ax = fabsf(x);
    float e  = __expf(-2.f*ax);
    float t  = __fdividef(1.f - e, 1.f + e);
    return (x < 0.f) ? -t : t;
}

// interleaved column position for gate row g = role*64 + elem  ->  3*elem + role
__device__ __forceinline__ int ilv(int g){ return 3*(g & 63) + (g >> 6); }

// ---------- 1) embedding-bag sums ----------
__global__ void embed_kernel(const int* __restrict__ titles,
                             const int* __restrict__ contents,
                             const float* __restrict__ emb)
{
    int idx = blockIdx.x*blockDim.x + threadIdx.x;
    if (idx >= ROWS_ALL*75) return;          // 75 float2 per row (D=150)
    int row = idx / 75;
    int dp  = idx - row*75;

    const int* ip; int stride;
    if (row < ROWS_T){ int n = row >> 5, t = row & 31;  ip = titles   + (n*6)*32  + t; stride = 32; }
    else             { int r = row - ROWS_T;
                       int n = r >> 7,   t = r & 127;   ip = contents + (n*6)*128 + t; stride = 128; }

    float ax = 0.f, ay = 0.f;
    #pragma unroll
    for (int i = 0; i < 6; i++){
        int ix = ip[i*stride];
        if (ix != 0){
            float2 v = *(const float2*)(emb + (size_t)ix*DD + 2*dp);
            ax += v.x; ay += v.y;
        }
    }
    *(float2*)(g_X + (size_t)row*DD + 2*dp) = make_float2(ax, ay);
}

// ---------- 2a) layer-0 input projection GEMM (K=150), dup-x, interleaved store ----------
__global__ void __launch_bounds__(256, 3) xg_gemm150(const float* __restrict__ W,
                                                     const float* __restrict__ bias)
{
    __shared__ float  sw [30*194];       // W chunk transposed: sw[kk*194 + g]
    __shared__ float2 sxd[64*31];        // X chunk, duplicated: (x,x) pairs
    int tid = threadIdx.x;
    int tx = tid & 31, ty = tid >> 5;
    int r0 = blockIdx.x * 64;

    unsigned long long acc[8][3];
    #pragma unroll
    for (int r = 0; r < 8; r++)
        #pragma unroll
        for (int c = 0; c < 3; c++) acc[r][c] = 0ull;

    for (int k0 = 0; k0 < 150; k0 += 30){
        for (int i = tid; i < 30*192; i += 256){
            int gg = i/30, kk = i - gg*30;
            sw[kk*194 + gg] = W[gg*150 + k0 + kk];
        }
        for (int i = tid; i < 64*30; i += 256){
            int rr = i/30, kk = i - rr*30;
            float v = g_X[(size_t)(r0+rr)*150 + k0 + kk];
            sxd[rr*31 + kk] = make_float2(v, v);
        }
        __syncthreads();
        #pragma unroll 6
        for (int kk = 0; kk < 30; kk++){
            unsigned long long w2[3];
            #pragma unroll
            for (int c = 0; c < 3; c++)
                w2[c] = *(const unsigned long long*)&sw[kk*194 + tx*6 + 2*c];
            #pragma unroll
            for (int r = 0; r < 8; r++){
                unsigned long long x2 = *(const unsigned long long*)&sxd[(ty*8 + r)*31 + kk];
                #pragma unroll
                for (int c = 0; c < 3; c++) fma2(acc[r][c], w2[c], x2);
            }
        }
        __syncthreads();
    }
    #pragma unroll
    for (int r = 0; r < 8; r++){
        int row = r0 + ty*8 + r;
        #pragma unroll
        for (int c = 0; c < 3; c++){
            float lo, hi;
            asm("mov.b64 {%0,%1}, %2;" : "=f"(lo), "=f"(hi) : "l"(acc[r][c]));
            int g0 = tx*6 + 2*c;
            g_xg[(size_t)row*GG + ilv(g0)]   = lo + bias[g0];
            g_xg[(size_t)row*GG + ilv(g0+1)] = hi + bias[g0+1];
        }
    }
}

// ---------- 2b) K=64 input projection GEMM (layers 1+), dup-x, interleaved store ----------
__global__ void __launch_bounds__(256, 3) xg_gemm64(const float* __restrict__ X,
                                                    const float* __restrict__ W,
                                                    const float* __restrict__ bias)
{
    __shared__ float  sw [32*194];       // W chunk transposed
    __shared__ float2 sxd[64*33];        // X chunk, duplicated pairs
    int tid = threadIdx.x;
    int tx = tid & 31, ty = tid >> 5;
    int r0 = blockIdx.x * 64;

    unsigned long long acc[8][3];
    #pragma unroll
    for (int r = 0; r < 8; r++)
        #pragma unroll
        for (int c = 0; c < 3; c++) acc[r][c] = 0ull;

    #pragma unroll
    for (int k0 = 0; k0 < 64; k0 += 32){
        for (int i = tid; i < 32*192; i += 256){
            int gg = i >> 5, kk = i & 31;
            sw[kk*194 + gg] = W[gg*64 + k0 + kk];
        }
        for (int i = tid; i < 64*32; i += 256){
            int rr = i >> 5, kk = i & 31;
            float v = X[(size_t)(r0+rr)*64 + k0 + kk];
            sxd[rr*33 + kk] = make_float2(v, v);
        }
        __syncthreads();
        #pragma unroll 8
        for (int kk = 0; kk < 32; kk++){
            unsigned long long w2[3];
            #pragma unroll
            for (int c = 0; c < 3; c++)
                w2[c] = *(const unsigned long long*)&sw[kk*194 + tx*6 + 2*c];
            #pragma unroll
            for (int r = 0; r < 8; r++){
                unsigned long long x2 = *(const unsigned long long*)&sxd[(ty*8 + r)*33 + kk];
                #pragma unroll
                for (int c = 0; c < 3; c++) fma2(acc[r][c], w2[c], x2);
            }
        }
        __syncthreads();
    }
    #pragma unroll
    for (int r = 0; r < 8; r++){
        int row = r0 + ty*8 + r;
        #pragma unroll
        for (int c = 0; c < 3; c++){
            float lo, hi;
            asm("mov.b64 {%0,%1}, %2;" : "=f"(lo), "=f"(hi) : "l"(acc[r][c]));
            int g0 = tx*6 + 2*c;
            g_xg[(size_t)row*GG + ilv(g0)]   = lo + bias[g0];
            g_xg[(size_t)row*GG + ilv(g0+1)] = hi + bias[g0+1];
        }
    }
}

// ---------- 3) GRU recurrence: h-matvec only, lane-triple gates, 1 barrier/step ----------
// 224 threads = 7 warps; lane triple (3k,3k+1,3k+2) of warp w owns element
// i = 10*w + k with roles r,z,n. Thread holds only its Whh row (64 regs) ->
// 2 CTAs/SM. xg read from gmem with distance-1 prefetch.
// mode 0: info mid (X layout), mode 1: info final (X in, concat out),
// mode 2: comb (concat, T=160). Info modes: content segment then title segment.
template<int NSEQ>
__global__ void __launch_bounds__(224, 2) gru_rec(
    const float* __restrict__ xg,
    const float* __restrict__ Whh, const float* __restrict__ bhh,
    float* __restrict__ yout, float* __restrict__ hid,
    int mode, int layer)
{
    __shared__ __align__(16) float sh_h[2][NSEQ][64];

    const int tid  = threadIdx.x;
    const int w    = tid >> 5, l = tid & 31;
    const int kk   = w*10 + l/3;
    const int role = l % 3;
    const bool valid = (l < 30) && (kk < 64);
    const int elem = valid ? kk : 0;
    const int row  = role*64 + elem;                         // gate row owned
    const int col  = (w*30 + l < GG) ? (w*30 + l) : (GG-1);  // interleaved xg col

    unsigned long long wh[32];
    {   const float2* p = (const float2*)(Whh + row*HH);
        #pragma unroll
        for (int j = 0; j < 32; j++){ float2 v = __ldg(p + j); wh[j] = pk2(v.x, v.y); }
    }
    const float bh_ = bhh[row];

    const int n0 = blockIdx.x * NSEQ;
    const int NSEG = (mode == 2) ? 1 : 2;

    for (int seg = 0; seg < NSEG; seg++){
        int T;
        int ibase[NSEQ], ob[NSEQ];
        if (mode == 2){
            T = LSEQ;
            #pragma unroll
            for (int s = 0; s < NSEQ; s++){ ibase[s] = (n0+s)*LSEQ; ob[s] = ibase[s]; }
        } else if (seg == 0){   // content
            T = LCC;
            #pragma unroll
            for (int s = 0; s < NSEQ; s++){
                ibase[s] = ROWS_T + (n0+s)*LCC;
                ob[s] = (mode == 1) ? (n0+s)*LSEQ + LTT : ibase[s];
            }
        } else {                // titles
            T = LTT;
            #pragma unroll
            for (int s = 0; s < NSEQ; s++){
                ibase[s] = (n0+s)*LTT;
                ob[s] = (mode == 1) ? (n0+s)*LSEQ : ibase[s];
            }
        }

        for (int idx = tid; idx < NSEQ*64; idx += 224)
            sh_h[0][idx >> 6][idx & 63] = 0.f;

        float axc[NSEQ];
        #pragma unroll
        for (int s = 0; s < NSEQ; s++)
            axc[s] = __ldg(xg + (size_t)ibase[s]*GG + col);
        __syncthreads();

        int p = 0;
        for (int t = 0; t < T; t++){
            // prefetch next step's xg early
            float axn[NSEQ];
            #pragma unroll
            for (int s = 0; s < NSEQ; s++)
                axn[s] = (t+1 < T) ? __ldg(xg + (size_t)(ibase[s]+t+1)*GG + col) : 0.f;

            // h-matvec
            unsigned long long accH[NSEQ];
            #pragma unroll
            for (int s = 0; s < NSEQ; s++) accH[s] = 0ull;
            #pragma unroll
            for (int j = 0; j < 16; j++){
                #pragma unroll
                for (int s = 0; s < NSEQ; s++){
                    ulonglong2 h4 = ((const ulonglong2*)sh_h[p][s])[j];
                    fma2(accH[s], wh[2*j],   h4.x);
                    fma2(accH[s], wh[2*j+1], h4.y);
                }
            }

            float v[NSEQ], ax_[NSEQ], ah_[NSEQ];
            #pragma unroll
            for (int s = 0; s < NSEQ; s++){
                ah_[s] = bh_ + upk_sum(accH[s]);
                ax_[s] = axc[s];
                v[s]   = sigmoidf_(ax_[s] + ah_[s]);     // meaningful for r/z lanes
            }

            // n-lanes gather r,z via shfl; compute tanh + h update
            #pragma unroll
            for (int s = 0; s < NSEQ; s++){
                float rv = __shfl_sync(0xFFFFFFFFu, v[s], (l+30) & 31);   // lane l-2
                float zv = __shfl_sync(0xFFFFFFFFu, v[s], (l+31) & 31);   // lane l-1
                float nn = tanhf_(ax_[s] + rv*ah_[s]);
                float hold = sh_h[p][s][elem];
                float hnew = zv*(hold - nn) + nn;
                if (role == 2 && valid){
                    sh_h[p^1][s][elem] = hnew;
                    yout[(size_t)(ob[s] + t)*HH + elem] = hnew;
                }
            }
            __syncthreads();
            #pragma unroll
            for (int s = 0; s < NSEQ; s++) axc[s] = axn[s];
            p ^= 1;
        }

        if (mode == 2 && hid != nullptr && role == 2 && valid){
            #pragma unroll
            for (int s = 0; s < NSEQ; s++){
                int n = n0 + s;
                int bi = n >> 6, sidx = n & 63;
                hid[(size_t)(((bi*4 + layer)*64 + sidx)*64) + elem] = sh_h[p][s][elem];
            }
        }
        if (seg + 1 < NSEG) __syncthreads();
    }
}

// ---------- 4) prices passthrough ----------
__global__ void tail_kernel(const float* __restrict__ prices, float* __restrict__ out){
    int i = threadIdx.x;
    if (i < 512) out[i] = prices[i];
}

extern "C" void kernel_launch(void* const* d_in, const int* in_sizes, int n_in,
                              void* d_out, int out_size)
{
    const int*   titles   = (const int*)  d_in[0];
    const int*   contents = (const int*)  d_in[1];
    const float* prices   = (const float*)d_in[2];
    const float* emb      = (const float*)d_in[3];
    const float* iWih0    = (const float*)d_in[4];
    const float* iWhh0    = (const float*)d_in[5];
    const float* ibih0    = (const float*)d_in[6];
    const float* ibhh0    = (const float*)d_in[7];
    const float* iWih     = (const float*)d_in[8];   // [3][192][64]
    const float* iWhh     = (const float*)d_in[9];
    const float* ibih     = (const float*)d_in[10];  // [3][192]
    const float* ibhh     = (const float*)d_in[11];
    const float* cWih     = (const float*)d_in[12];  // [4][192][64]
    const float* cWhh     = (const float*)d_in[13];
    const float* cbih     = (const float*)d_in[14];
    const float* cbhh     = (const float*)d_in[15];

    float* out = (float*)d_out;
    float* hid = out + (size_t)8*64*160*64;          // encoder_hidden region
    float* pr  = hid + (size_t)8*4*64*64;            // prices region

    float *pXG = nullptr, *pA = nullptr, *pB = nullptr;
    cudaGetSymbolAddress((void**)&pXG, g_xg);
    cudaGetSymbolAddress((void**)&pA,  g_A);
    cudaGetSymbolAddress((void**)&pB,  g_B);

    const int GRID_G = ROWS_ALL/64;   // 1280

    // 1) embedding bags
    embed_kernel<<<(ROWS_ALL*75 + 255)/256, 256>>>(titles, contents, emb);

    // info layer 0
    xg_gemm150<<<GRID_G, 256>>>(iWih0, ibih0);
    gru_rec<2><<<256, 224>>>(pXG, iWhh0, ibhh0, pA, nullptr, 0, 0);

    // info layers 1..3; layer 3 writes concat layout
    xg_gemm64<<<GRID_G, 256>>>(pA, iWih + 0*GG*HH, ibih + 0*GG);
    gru_rec<2><<<256, 224>>>(pXG, iWhh + 0*GG*HH, ibhh + 0*GG, pB, nullptr, 0, 0);

    xg_gemm64<<<GRID_G, 256>>>(pB, iWih + 1*GG*HH, ibih + 1*GG);
    gru_rec<2><<<256, 224>>>(pXG, iWhh + 1*GG*HH, ibhh + 1*GG, pA, nullptr, 0, 0);

    xg_gemm64<<<GRID_G, 256>>>(pA, iWih + 2*GG*HH, ibih + 2*GG);
    gru_rec<2><<<256, 224>>>(pXG, iWhh + 2*GG*HH, ibhh + 2*GG, pB, nullptr, 1, 0);

    // comb layers 0..3 (concat layout, T=160); final layer writes encoder_outputs
    xg_gemm64<<<GRID_G, 256>>>(pB, cWih + 0*GG*HH, cbih + 0*GG);
    gru_rec<2><<<256, 224>>>(pXG, cWhh + 0*GG*HH, cbhh + 0*GG, pA,  hid, 2, 0);

    xg_gemm64<<<GRID_G, 256>>>(pA, cWih + 1*GG*HH, cbih + 1*GG);
    gru_rec<2><<<256, 224>>>(pXG, cWhh + 1*GG*HH, cbhh + 1*GG, pB,  hid, 2, 1);

    xg_gemm64<<<GRID_G, 256>>>(pB, cWih + 2*GG*HH, cbih + 2*GG);
    gru_rec<2><<<256, 224>>>(pXG, cWhh + 2*GG*HH, cbhh + 2*GG, pA,  hid, 2, 2);

    xg_gemm64<<<GRID_G, 256>>>(pA, cWih + 3*GG*HH, cbih + 3*GG);
    gru_rec<2><<<256, 224>>>(pXG, cWhh + 3*GG*HH, cbhh + 3*GG, out, hid, 2, 3);

    // prices passthrough
    tail_kernel<<<1, 512>>>(prices, pr);
}

// round 10
// speedup vs baseline: 1.5121x; 1.2758x over previous
#include <cuda_runtime.h>
#include <cstdint>

// Problem dims
#define NS   512                 // B*S
#define DD   150
#define HH   64
#define GG   192                 // 3H
#define LTT  32
#define LCC  128
#define LSEQ 160                 // LTT + LCC
#define ROWS_T (NS*LTT)          // 16384
#define ROWS_ALL (NS*(LTT+LCC))  // 81920

// Scratch (device globals; no runtime alloc allowed)
__device__ float g_X [ROWS_ALL*DD];   // embed sums (layer0 input)
__device__ float g_xg[ROWS_ALL*GG];   // per-layer input projection, plain [row][gate]
__device__ float g_A [ROWS_ALL*HH];
__device__ float g_B [ROWS_ALL*HH];

// ---------- f32x2 helpers ----------
__device__ __forceinline__ unsigned long long pk2(float a, float b){
    unsigned long long r; asm("mov.b64 %0,{%1,%2};" : "=l"(r) : "f"(a), "f"(b)); return r;
}
__device__ __forceinline__ void fma2(unsigned long long &acc, unsigned long long a, unsigned long long b){
    asm("fma.rn.f32x2 %0, %1, %2, %0;" : "+l"(acc) : "l"(a), "l"(b));
}
__device__ __forceinline__ float upk_sum(unsigned long long a){
    float x, y; asm("mov.b64 {%0,%1}, %2;" : "=f"(x), "=f"(y) : "l"(a)); return x + y;
}
__device__ __forceinline__ float sigmoidf_(float x){
    return __fdividef(1.f, 1.f + __expf(-x));
}
__device__ __forceinline__ float tanhf_(float x){
    float ax = fabsf(x);
    float e  = __expf(-2.f*ax);
    float t  = __fdividef(1.f - e, 1.f + e);
    return (x < 0.f) ? -t : t;
}

// ---------- 1) embedding-bag sums ----------
__global__ void embed_kernel(const int* __restrict__ titles,
                             const int* __restrict__ contents,
                             const float* __restrict__ emb)
{
    int idx = blockIdx.x*blockDim.x + threadIdx.x;
    if (idx >= ROWS_ALL*75) return;          // 75 float2 per row (D=150)
    int row = idx / 75;
    int dp  = idx - row*75;

    const int* ip; int stride;
    if (row < ROWS_T){ int n = row >> 5, t = row & 31;  ip = titles   + (n*6)*32  + t; stride = 32; }
    else             { int r = row - ROWS_T;
                       int n = r >> 7,   t = r & 127;   ip = contents + (n*6)*128 + t; stride = 128; }

    float ax = 0.f, ay = 0.f;
    #pragma unroll
    for (int i = 0; i < 6; i++){
        int ix = ip[i*stride];
        if (ix != 0){
            float2 v = *(const float2*)(emb + (size_t)ix*DD + 2*dp);
            ax += v.x; ay += v.y;
        }
    }
    *(float2*)(g_X + (size_t)row*DD + 2*dp) = make_float2(ax, ay);
}

// ---------- 2a) layer-0 input projection GEMM (K=150), fp32, plain store ----------
__global__ void __launch_bounds__(256, 3) xg_gemm150(const float* __restrict__ W,
                                                     const float* __restrict__ bias)
{
    __shared__ float  sw [30*194];
    __shared__ float2 sxd[64*31];
    int tid = threadIdx.x;
    int tx = tid & 31, ty = tid >> 5;
    int r0 = blockIdx.x * 64;

    unsigned long long acc[8][3];
    #pragma unroll
    for (int r = 0; r < 8; r++)
        #pragma unroll
        for (int c = 0; c < 3; c++) acc[r][c] = 0ull;

    for (int k0 = 0; k0 < 150; k0 += 30){
        for (int i = tid; i < 30*192; i += 256){
            int gg = i/30, kk = i - gg*30;
            sw[kk*194 + gg] = W[gg*150 + k0 + kk];
        }
        for (int i = tid; i < 64*30; i += 256){
            int rr = i/30, kk = i - rr*30;
            float v = g_X[(size_t)(r0+rr)*150 + k0 + kk];
            sxd[rr*31 + kk] = make_float2(v, v);
        }
        __syncthreads();
        #pragma unroll 6
        for (int kk = 0; kk < 30; kk++){
            unsigned long long w2[3];
            #pragma unroll
            for (int c = 0; c < 3; c++)
                w2[c] = *(const unsigned long long*)&sw[kk*194 + tx*6 + 2*c];
            #pragma unroll
            for (int r = 0; r < 8; r++){
                unsigned long long x2 = *(const unsigned long long*)&sxd[(ty*8 + r)*31 + kk];
                #pragma unroll
                for (int c = 0; c < 3; c++) fma2(acc[r][c], w2[c], x2);
            }
        }
        __syncthreads();
    }
    #pragma unroll
    for (int r = 0; r < 8; r++){
        int row = r0 + ty*8 + r;
        #pragma unroll
        for (int c = 0; c < 3; c++){
            float lo, hi;
            asm("mov.b64 {%0,%1}, %2;" : "=f"(lo), "=f"(hi) : "l"(acc[r][c]));
            int g0 = tx*6 + 2*c;
            float2 o; o.x = lo + bias[g0]; o.y = hi + bias[g0+1];
            *(float2*)(g_xg + (size_t)row*GG + g0) = o;
        }
    }
}

// ---------- 2b) K=64 input projection GEMM (layers 1+), fp32, plain store ----------
__global__ void __launch_bounds__(256, 3) xg_gemm64(const float* __restrict__ X,
                                                    const float* __restrict__ W,
                                                    const float* __restrict__ bias)
{
    __shared__ float  sw [32*194];
    __shared__ float2 sxd[64*33];
    int tid = threadIdx.x;
    int tx = tid & 31, ty = tid >> 5;
    int r0 = blockIdx.x * 64;

    unsigned long long acc[8][3];
    #pragma unroll
    for (int r = 0; r < 8; r++)
        #pragma unroll
        for (int c = 0; c < 3; c++) acc[r][c] = 0ull;

    #pragma unroll
    for (int k0 = 0; k0 < 64; k0 += 32){
        for (int i = tid; i < 32*192; i += 256){
            int gg = i >> 5, kk = i & 31;
            sw[kk*194 + gg] = W[gg*64 + k0 + kk];
        }
        for (int i = tid; i < 64*32; i += 256){
            int rr = i >> 5, kk = i & 31;
            float v = X[(size_t)(r0+rr)*64 + k0 + kk];
            sxd[rr*33 + kk] = make_float2(v, v);
        }
        __syncthreads();
        #pragma unroll 8
        for (int kk = 0; kk < 32; kk++){
            unsigned long long w2[3];
            #pragma unroll
            for (int c = 0; c < 3; c++)
                w2[c] = *(const unsigned long long*)&sw[kk*194 + tx*6 + 2*c];
            #pragma unroll
            for (int r = 0; r < 8; r++){
                unsigned long long x2 = *(const unsigned long long*)&sxd[(ty*8 + r)*33 + kk];
                #pragma unroll
                for (int c = 0; c < 3; c++) fma2(acc[r][c], w2[c], x2);
            }
        }
        __syncthreads();
    }
    #pragma unroll
    for (int r = 0; r < 8; r++){
        int row = r0 + ty*8 + r;
        #pragma unroll
        for (int c = 0; c < 3; c++){
            float lo, hi;
            asm("mov.b64 {%0,%1}, %2;" : "=f"(lo), "=f"(hi) : "l"(acc[r][c]));
            int g0 = tx*6 + 2*c;
            float2 o; o.x = lo + bias[g0]; o.y = hi + bias[g0+1];
            *(float2*)(g_xg + (size_t)row*GG + g0) = o;
        }
    }
}

// ---------- 3) GRU recurrence: 64-thread groups, thread owns r,z,n of one element ----------
// Block 256 = 4 groups of 64 threads (2 warps). Group advances ONE sequence;
// thread k owns gate rows k (r), 64+k (z), 128+k (n) and computes all three
// gates plus the h-update locally (no shuffles, no exchange). One named barrier
// (bar.sync grp,64) per step; h double-buffered in shared, broadcast reads.
// mode 0: info mid (X layout out), mode 1: info final (concat out), mode 2: comb.
// Info modes: each group runs content stream (T=128) then title stream (T=32).
__global__ void __launch_bounds__(256, 1) gru_rec64(
    const float* __restrict__ xg,
    const float* __restrict__ Whh, const float* __restrict__ bhh,
    float* __restrict__ yout, float* __restrict__ hid,
    int mode, int layer)
{
    __shared__ __align__(16) float sh_h[4][2][64];

    const int tid = threadIdx.x;
    const int grp = tid >> 6, k = tid & 63;
    const int gid = blockIdx.x*4 + grp;        // 0..511

    // weight rows r,z,n -> registers (3 x 32 f32x2)
    unsigned long long wr[32], wz[32], wn[32];
    {
        const float2* pr_ = (const float2*)(Whh + (size_t)k*HH);
        const float2* pz_ = (const float2*)(Whh + (size_t)(64 + k)*HH);
        const float2* pn_ = (const float2*)(Whh + (size_t)(128 + k)*HH);
        #pragma unroll
        for (int j = 0; j < 32; j++){
            float2 a = __ldg(pr_ + j); wr[j] = pk2(a.x, a.y);
            float2 b = __ldg(pz_ + j); wz[j] = pk2(b.x, b.y);
            float2 c = __ldg(pn_ + j); wn[j] = pk2(c.x, c.y);
        }
    }
    const float br_ = bhh[k], bz_ = bhh[64 + k], bn_ = bhh[128 + k];

    const int NSEG = (mode == 2) ? 1 : 2;
    float hk = 0.f;

    for (int seg = 0; seg < NSEG; seg++){
        int T, ibase, ob;
        if (mode == 2){        ibase = gid*LSEQ;            T = LSEQ; ob = ibase; }
        else if (seg == 0){    ibase = ROWS_T + gid*LCC;    T = LCC;
                               ob = (mode == 1) ? gid*LSEQ + LTT : ibase; }
        else {                 ibase = gid*LTT;             T = LTT;
                               ob = (mode == 1) ? gid*LSEQ : ibase; }

        hk = 0.f;
        sh_h[grp][0][k] = 0.f;

        int xoff = ibase*GG + k;
        float axr = __ldg(xg + xoff);
        float axz = __ldg(xg + xoff + 64);
        float axn = __ldg(xg + xoff + 128);
        asm volatile("bar.sync %0, %1;" :: "r"(grp), "r"(64) : "memory");

        int p = 0;
        for (int t = 0; t < T; t++){
            // prefetch next step's xg
            float nxr = 0.f, nxz = 0.f, nxn = 0.f;
            if (t+1 < T){
                int xo = (ibase + t + 1)*GG + k;
                nxr = __ldg(xg + xo);
                nxz = __ldg(xg + xo + 64);
                nxn = __ldg(xg + xo + 128);
            }

            // three matvecs against broadcast h
            unsigned long long ar = 0ull, az = 0ull, an = 0ull;
            const ulonglong2* hp = (const ulonglong2*)sh_h[grp][p];
            #pragma unroll
            for (int j = 0; j < 16; j++){
                ulonglong2 h4 = hp[j];
                fma2(ar, wr[2*j],   h4.x);  fma2(ar, wr[2*j+1], h4.y);
                fma2(az, wz[2*j],   h4.x);  fma2(az, wz[2*j+1], h4.y);
                fma2(an, wn[2*j],   h4.x);  fma2(an, wn[2*j+1], h4.y);
            }

            float gr = sigmoidf_(axr + br_ + upk_sum(ar));
            float gz = sigmoidf_(axz + bz_ + upk_sum(az));
            float gn = tanhf_(axn + gr*(bn_ + upk_sum(an)));
            hk = gz*(hk - gn) + gn;

            sh_h[grp][p^1][k] = hk;
            yout[(size_t)(ob + t)*HH + k] = hk;

            asm volatile("bar.sync %0, %1;" :: "r"(grp), "r"(64) : "memory");
            axr = nxr; axz = nxz; axn = nxn;
            p ^= 1;
        }
    }

    if (mode == 2 && hid != nullptr){
        int bi = gid >> 6, sidx = gid & 63;
        hid[(size_t)(((bi*4 + layer)*64 + sidx)*64) + k] = hk;
    }
}

// ---------- 4) prices passthrough ----------
__global__ void tail_kernel(const float* __restrict__ prices, float* __restrict__ out){
    int i = threadIdx.x;
    if (i < 512) out[i] = prices[i];
}

extern "C" void kernel_launch(void* const* d_in, const int* in_sizes, int n_in,
                              void* d_out, int out_size)
{
    const int*   titles   = (const int*)  d_in[0];
    const int*   contents = (const int*)  d_in[1];
    const float* prices   = (const float*)d_in[2];
    const float* emb      = (const float*)d_in[3];
    const float* iWih0    = (const float*)d_in[4];
    const float* iWhh0    = (const float*)d_in[5];
    const float* ibih0    = (const float*)d_in[6];
    const float* ibhh0    = (const float*)d_in[7];
    const float* iWih     = (const float*)d_in[8];   // [3][192][64]
    const float* iWhh     = (const float*)d_in[9];
    const float* ibih     = (const float*)d_in[10];  // [3][192]
    const float* ibhh     = (const float*)d_in[11];
    const float* cWih     = (const float*)d_in[12];  // [4][192][64]
    const float* cWhh     = (const float*)d_in[13];
    const float* cbih     = (const float*)d_in[14];
    const float* cbhh     = (const float*)d_in[15];

    float* out = (float*)d_out;
    float* hid = out + (size_t)8*64*160*64;          // encoder_hidden region
    float* pr  = hid + (size_t)8*4*64*64;            // prices region

    float *pXG = nullptr, *pA = nullptr, *pB = nullptr;
    cudaGetSymbolAddress((void**)&pXG, g_xg);
    cudaGetSymbolAddress((void**)&pA,  g_A);
    cudaGetSymbolAddress((void**)&pB,  g_B);

    const int GRID_G = ROWS_ALL/64;   // 1280

    // 1) embedding bags
    embed_kernel<<<(ROWS_ALL*75 + 255)/256, 256>>>(titles, contents, emb);

    // info layer 0
    xg_gemm150<<<GRID_G, 256>>>(iWih0, ibih0);
    gru_rec64<<<128, 256>>>(pXG, iWhh0, ibhh0, pA, nullptr, 0, 0);

    // info layers 1..3; layer 3 writes concat layout
    xg_gemm64<<<GRID_G, 256>>>(pA, iWih + 0*GG*HH, ibih + 0*GG);
    gru_rec64<<<128, 256>>>(pXG, iWhh + 0*GG*HH, ibhh + 0*GG, pB, nullptr, 0, 0);

    xg_gemm64<<<GRID_G, 256>>>(pB, iWih + 1*GG*HH, ibih + 1*GG);
    gru_rec64<<<128, 256>>>(pXG, iWhh + 1*GG*HH, ibhh + 1*GG, pA, nullptr, 0, 0);

    xg_gemm64<<<GRID_G, 256>>>(pA, iWih + 2*GG*HH, ibih + 2*GG);
    gru_rec64<<<128, 256>>>(pXG, iWhh + 2*GG*HH, ibhh + 2*GG, pB, nullptr, 1, 0);

    // comb layers 0..3 (concat layout, T=160); final layer writes encoder_outputs
    xg_gemm64<<<GRID_G, 256>>>(pB, cWih + 0*GG*HH, cbih + 0*GG);
    gru_rec64<<<128, 256>>>(pXG, cWhh + 0*GG*HH, cbhh + 0*GG, pA,  hid, 2, 0);

    xg_gemm64<<<GRID_G, 256>>>(pA, cWih + 1*GG*HH, cbih + 1*GG);
    gru_rec64<<<128, 256>>>(pXG, cWhh + 1*GG*HH, cbhh + 1*GG, pB,  hid, 2, 1);

    xg_gemm64<<<GRID_G, 256>>>(pB, cWih + 2*GG*HH, cbih + 2*GG);
    gru_rec64<<<128, 256>>>(pXG, cWhh + 2*GG*HH, cbhh + 2*GG, pA,  hid, 2, 2);

    xg_gemm64<<<GRID_G, 256>>>(pA, cWih + 3*GG*HH, cbih + 3*GG);
    gru_rec64<<<128, 256>>>(pXG, cWhh + 3*GG*HH, cbhh + 3*GG, out, hid, 2, 3);

    // prices passthrough
    tail_kernel<<<1, 512>>>(prices, pr);
}

// round 12
// speedup vs baseline: 1.5634x; 1.0340x over previous
#include <cuda_runtime.h>
#include <cstdint>

// Problem dims
#define NS   512                 // B*S
#define DD   150
#define HH   64
#define GG   192                 // 3H
#define LTT  32
#define LCC  128
#define LSEQ 160                 // LTT + LCC
#define ROWS_T (NS*LTT)          // 16384
#define ROWS_ALL (NS*(LTT+LCC))  // 81920

// Scratch (device globals; no runtime alloc allowed)
__device__ float g_X [ROWS_ALL*DD];   // embed sums (layer0 input)
__device__ float g_xg[ROWS_ALL*GG];   // per-layer input projection, plain [row][gate]
__device__ float g_A [ROWS_ALL*HH];
__device__ float g_B [ROWS_ALL*HH];

// ---------- f32x2 helpers ----------
__device__ __forceinline__ unsigned long long pk2(float a, float b){
    unsigned long long r; asm("mov.b64 %0,{%1,%2};" : "=l"(r) : "f"(a), "f"(b)); return r;
}
__device__ __forceinline__ void fma2(unsigned long long &acc, unsigned long long a, unsigned long long b){
    asm("fma.rn.f32x2 %0, %1, %2, %0;" : "+l"(acc) : "l"(a), "l"(b));
}
__device__ __forceinline__ float upk_sum(unsigned long long a){
    float x, y; asm("mov.b64 {%0,%1}, %2;" : "=f"(x), "=f"(y) : "l"(a)); return x + y;
}
__device__ __forceinline__ float sigmoidf_(float x){
    return __fdividef(1.f, 1.f + __expf(-x));
}
__device__ __forceinline__ float tanhf_(float x){
    float ax = fabsf(x);
    float e  = __expf(-2.f*ax);
    float t  = __fdividef(1.f - e, 1.f + e);
    return (x < 0.f) ? -t : t;
}

// ---------- 1) embedding-bag sums ----------
__global__ void embed_kernel(const int* __restrict__ titles,
                             const int* __restrict__ contents,
                             const float* __restrict__ emb)
{
    int idx = blockIdx.x*blockDim.x + threadIdx.x;
    if (idx >= ROWS_ALL*75) return;          // 75 float2 per row (D=150)
    int row = idx / 75;
    int dp  = idx - row*75;

    const int* ip; int stride;
    if (row < ROWS_T){ int n = row >> 5, t = row & 31;  ip = titles   + (n*6)*32  + t; stride = 32; }
    else             { int r = row - ROWS_T;
                       int n = r >> 7,   t = r & 127;   ip = contents + (n*6)*128 + t; stride = 128; }

    float ax = 0.f, ay = 0.f;
    #pragma unroll
    for (int i = 0; i < 6; i++){
        int ix = ip[i*stride];
        if (ix != 0){
            float2 v = *(const float2*)(emb + (size_t)ix*DD + 2*dp);
            ax += v.x; ay += v.y;
        }
    }
    *(float2*)(g_X + (size_t)row*DD + 2*dp) = make_float2(ax, ay);
}

// ---------- 2a) layer-0 input projection GEMM (K=150), fp32, plain store ----------
__global__ void __launch_bounds__(256, 3) xg_gemm150(const float* __restrict__ W,
                                                     const float* __restrict__ bias)
{
    __shared__ float  sw [30*194];
    __shared__ float2 sxd[64*31];
    int tid = threadIdx.x;
    int tx = tid & 31, ty = tid >> 5;
    int r0 = blockIdx.x * 64;

    unsigned long long acc[8][3];
    #pragma unroll
    for (int r = 0; r < 8; r++)
        #pragma unroll
        for (int c = 0; c < 3; c++) acc[r][c] = 0ull;

    for (int k0 = 0; k0 < 150; k0 += 30){
        for (int i = tid; i < 30*192; i += 256){
            int gg = i/30, kk = i - gg*30;
            sw[kk*194 + gg] = W[gg*150 + k0 + kk];
        }
        for (int i = tid; i < 64*30; i += 256){
            int rr = i/30, kk = i - rr*30;
            float v = g_X[(size_t)(r0+rr)*150 + k0 + kk];
            sxd[rr*31 + kk] = make_float2(v, v);
        }
        __syncthreads();
        #pragma unroll 6
        for (int kk = 0; kk < 30; kk++){
            unsigned long long w2[3];
            #pragma unroll
            for (int c = 0; c < 3; c++)
                w2[c] = *(const unsigned long long*)&sw[kk*194 + tx*6 + 2*c];
            #pragma unroll
            for (int r = 0; r < 8; r++){
                unsigned long long x2 = *(const unsigned long long*)&sxd[(ty*8 + r)*31 + kk];
                #pragma unroll
                for (int c = 0; c < 3; c++) fma2(acc[r][c], w2[c], x2);
            }
        }
        __syncthreads();
    }
    #pragma unroll
    for (int r = 0; r < 8; r++){
        int row = r0 + ty*8 + r;
        #pragma unroll
        for (int c = 0; c < 3; c++){
            float lo, hi;
            asm("mov.b64 {%0,%1}, %2;" : "=f"(lo), "=f"(hi) : "l"(acc[r][c]));
            int g0 = tx*6 + 2*c;
            float2 o; o.x = lo + bias[g0]; o.y = hi + bias[g0+1];
            *(float2*)(g_xg + (size_t)row*GG + g0) = o;
        }
    }
}

// ---------- 2b) K=64 projection GEMM, k-paired f32x2, no duplication ----------
// Tile 64 rows x 96 cols (half of GG). Grid = (ROWS_ALL/64)*2.
// Thread (tx,ty): rows ty*8..+7, cols c0 + tx + 32*c (c=0..2).
// acc2[r][c] accumulates (even-k, odd-k) partials; reduced at epilogue.
// Single smem fill (full K=64), ONE barrier, 16 fully-unrolled 4-k blocks:
// per block 3 w-LDS.128 + 8 x-LDS.128 (broadcast) + 48 FFMA2.
#define SWP 68   // padded row stride (floats): 272B, 16B-aligned
__global__ void __launch_bounds__(256, 3) xg_gemm64(const float* __restrict__ X,
                                                    const float* __restrict__ W,
                                                    const float* __restrict__ bias)
{
    __shared__ float sw[96*SWP];
    __shared__ float sx[64*SWP];
    const int tid = threadIdx.x;
    const int tx = tid & 31, ty = tid >> 5;
    const int r0 = (blockIdx.x >> 1) * 64;
    const int c0 = (blockIdx.x & 1) * 96;

    // fill W half [96 gates x 64 k] and X tile [64 rows x 64 k], float4 copies
    for (int i = tid; i < 96*16; i += 256){
        int g = i >> 4, kq = i & 15;
        float4 v = *(const float4*)(W + (size_t)(c0 + g)*64 + kq*4);
        *(float4*)(sw + g*SWP + kq*4) = v;
    }
    for (int i = tid; i < 64*16; i += 256){
        int r = i >> 4, kq = i & 15;
        float4 v = *(const float4*)(X + (size_t)(r0 + r)*64 + kq*4);
        *(float4*)(sx + r*SWP + kq*4) = v;
    }
    __syncthreads();

    unsigned long long acc[8][3];
    #pragma unroll
    for (int r = 0; r < 8; r++)
        #pragma unroll
        for (int c = 0; c < 3; c++) acc[r][c] = 0ull;

    #pragma unroll
    for (int k4 = 0; k4 < 16; k4++){
        ulonglong2 wv[3];
        #pragma unroll
        for (int c = 0; c < 3; c++)
            wv[c] = *(const ulonglong2*)(sw + (tx + 32*c)*SWP + k4*4);
        #pragma unroll
        for (int r = 0; r < 8; r++){
            ulonglong2 xv = *(const ulonglong2*)(sx + (ty*8 + r)*SWP + k4*4);
            #pragma unroll
            for (int c = 0; c < 3; c++){
                fma2(acc[r][c], wv[c].x, xv.x);
                fma2(acc[r][c], wv[c].y, xv.y);
            }
        }
    }

    #pragma unroll
    for (int r = 0; r < 8; r++){
        int row = r0 + ty*8 + r;
        #pragma unroll
        for (int c = 0; c < 3; c++){
            int col = c0 + tx + 32*c;
            g_xg[(size_t)row*GG + col] = upk_sum(acc[r][c]) + __ldg(bias + col);
        }
    }
}

// ---------- 3) GRU recurrence: 64-thread groups, thread owns r,z,n of one element ----------
// Block 256 = 4 groups of 64 threads (2 warps). Group advances ONE sequence;
// thread k owns gate rows k (r), 64+k (z), 128+k (n): computes all three gates
// and the h-update locally. One named barrier per step; h double-buffered in
// shared. Accumulators split into 2 chains each (depth 16) for latency.
// mode 0: info mid (X layout out), mode 1: info final (concat out), mode 2: comb.
__global__ void __launch_bounds__(256, 1) gru_rec64(
    const float* __restrict__ xg,
    const float* __restrict__ Whh, const float* __restrict__ bhh,
    float* __restrict__ yout, float* __restrict__ hid,
    int mode, int layer)
{
    __shared__ __align__(16) float sh_h[4][2][64];

    const int tid = threadIdx.x;
    const int grp = tid >> 6, k = tid & 63;
    const int gid = blockIdx.x*4 + grp;        // 0..511

    // weight rows r,z,n -> registers (3 x 32 f32x2)
    unsigned long long wr[32], wz[32], wn[32];
    {
        const float2* pr_ = (const float2*)(Whh + (size_t)k*HH);
        const float2* pz_ = (const float2*)(Whh + (size_t)(64 + k)*HH);
        const float2* pn_ = (const float2*)(Whh + (size_t)(128 + k)*HH);
        #pragma unroll
        for (int j = 0; j < 32; j++){
            float2 a = __ldg(pr_ + j); wr[j] = pk2(a.x, a.y);
            float2 b = __ldg(pz_ + j); wz[j] = pk2(b.x, b.y);
            float2 c = __ldg(pn_ + j); wn[j] = pk2(c.x, c.y);
        }
    }
    const float br_ = bhh[k], bz_ = bhh[64 + k], bn_ = bhh[128 + k];

    const int NSEG = (mode == 2) ? 1 : 2;
    float hk = 0.f;

    for (int seg = 0; seg < NSEG; seg++){
        int T, ibase, ob;
        if (mode == 2){        ibase = gid*LSEQ;            T = LSEQ; ob = ibase; }
        else if (seg == 0){    ibase = ROWS_T + gid*LCC;    T = LCC;
                               ob = (mode == 1) ? gid*LSEQ + LTT : ibase; }
        else {                 ibase = gid*LTT;             T = LTT;
                               ob = (mode == 1) ? gid*LSEQ : ibase; }

        hk = 0.f;
        sh_h[grp][0][k] = 0.f;

        int xoff = ibase*GG + k;
        float axr = __ldg(xg + xoff);
        float axz = __ldg(xg + xoff + 64);
        float axn = __ldg(xg + xoff + 128);
        asm volatile("bar.sync %0, %1;" :: "r"(grp), "r"(64) : "memory");

        int p = 0;
        for (int t = 0; t < T; t++){
            // prefetch next step's xg
            float nxr = 0.f, nxz = 0.f, nxn = 0.f;
            if (t+1 < T){
                int xo = (ibase + t + 1)*GG + k;
                nxr = __ldg(xg + xo);
                nxz = __ldg(xg + xo + 64);
                nxn = __ldg(xg + xo + 128);
            }

            // three matvecs, 2 chains each (depth 16)
            unsigned long long ar0 = 0ull, ar1 = 0ull;
            unsigned long long az0 = 0ull, az1 = 0ull;
            unsigned long long an0 = 0ull, an1 = 0ull;
            const ulonglong2* hp = (const ulonglong2*)sh_h[grp][p];
            #pragma unroll
            for (int j = 0; j < 16; j++){
                ulonglong2 h4 = hp[j];
                fma2(ar0, wr[2*j],   h4.x);  fma2(ar1, wr[2*j+1], h4.y);
                fma2(az0, wz[2*j],   h4.x);  fma2(az1, wz[2*j+1], h4.y);
                fma2(an0, wn[2*j],   h4.x);  fma2(an1, wn[2*j+1], h4.y);
            }

            float gr = sigmoidf_(axr + br_ + upk_sum(ar0) + upk_sum(ar1));
            float gz = sigmoidf_(axz + bz_ + upk_sum(az0) + upk_sum(az1));
            float gn = tanhf_(axn + gr*(bn_ + upk_sum(an0) + upk_sum(an1)));
            hk = gz*(hk - gn) + gn;

            sh_h[grp][p^1][k] = hk;
            yout[(size_t)(ob + t)*HH + k] = hk;

            asm volatile("bar.sync %0, %1;" :: "r"(grp), "r"(64) : "memory");
            axr = nxr; axz = nxz; axn = nxn;
            p ^= 1;
        }
    }

    if (mode == 2 && hid != nullptr){
        int bi = gid >> 6, sidx = gid & 63;
        hid[(size_t)(((bi*4 + layer)*64 + sidx)*64) + k] = hk;
    }
}

// ---------- 4) prices passthrough ----------
__global__ void tail_kernel(const float* __restrict__ prices, float* __restrict__ out){
    int i = threadIdx.x;
    if (i < 512) out[i] = prices[i];
}

extern "C" void kernel_launch(void* const* d_in, const int* in_sizes, int n_in,
                              void* d_out, int out_size)
{
    const int*   titles   = (const int*)  d_in[0];
    const int*   contents = (const int*)  d_in[1];
    const float* prices   = (const float*)d_in[2];
    const float* emb      = (const float*)d_in[3];
    const float* iWih0    = (const float*)d_in[4];
    const float* iWhh0    = (const float*)d_in[5];
    const float* ibih0    = (const float*)d_in[6];
    const float* ibhh0    = (const float*)d_in[7];
    const float* iWih     = (const float*)d_in[8];   // [3][192][64]
    const float* iWhh     = (const float*)d_in[9];
    const float* ibih     = (const float*)d_in[10];  // [3][192]
    const float* ibhh     = (const float*)d_in[11];
    const float* cWih     = (const float*)d_in[12];  // [4][192][64]
    const float* cWhh     = (const float*)d_in[13];
    const float* cbih     = (const float*)d_in[14];
    const float* cbhh     = (const float*)d_in[15];

    float* out = (float*)d_out;
    float* hid = out + (size_t)8*64*160*64;          // encoder_hidden region
    float* pr  = hid + (size_t)8*4*64*64;            // prices region

    float *pXG = nullptr, *pA = nullptr, *pB = nullptr;
    cudaGetSymbolAddress((void**)&pXG, g_xg);
    cudaGetSymbolAddress((void**)&pA,  g_A);
    cudaGetSymbolAddress((void**)&pB,  g_B);

    const int GRID_M = (ROWS_ALL/64)*2;   // 2560 (row-tile x col-half)

    // 1) embedding bags
    embed_kernel<<<(ROWS_ALL*75 + 255)/256, 256>>>(titles, contents, emb);

    // info layer 0
    xg_gemm150<<<ROWS_ALL/64, 256>>>(iWih0, ibih0);
    gru_rec64<<<128, 256>>>(pXG, iWhh0, ibhh0, pA, nullptr, 0, 0);

    // info layers 1..3; layer 3 writes concat layout
    xg_gemm64<<<GRID_M, 256>>>(pA, iWih + 0*GG*HH, ibih + 0*GG);
    gru_rec64<<<128, 256>>>(pXG, iWhh + 0*GG*HH, ibhh + 0*GG, pB, nullptr, 0, 0);

    xg_gemm64<<<GRID_M, 256>>>(pB, iWih + 1*GG*HH, ibih + 1*GG);
    gru_rec64<<<128, 256>>>(pXG, iWhh + 1*GG*HH, ibhh + 1*GG, pA, nullptr, 0, 0);

    xg_gemm64<<<GRID_M, 256>>>(pA, iWih + 2*GG*HH, ibih + 2*GG);
    gru_rec64<<<128, 256>>>(pXG, iWhh + 2*GG*HH, ibhh + 2*GG, pB, nullptr, 1, 0);

    // comb layers 0..3 (concat layout, T=160); final layer writes encoder_outputs
    xg_gemm64<<<GRID_M, 256>>>(pB, cWih + 0*GG*HH, cbih + 0*GG);
    gru_rec64<<<128, 256>>>(pXG, cWhh + 0*GG*HH, cbhh + 0*GG, pA,  hid, 2, 0);

    xg_gemm64<<<GRID_M, 256>>>(pA, cWih + 1*GG*HH, cbih + 1*GG);
    gru_rec64<<<128, 256>>>(pXG, cWhh + 1*GG*HH, cbhh + 1*GG, pB,  hid, 2, 1);

    xg_gemm64<<<GRID_M, 256>>>(pB, cWih + 2*GG*HH, cbih + 2*GG);
    gru_rec64<<<128, 256>>>(pXG, cWhh + 2*GG*HH, cbhh + 2*GG, pA,  hid, 2, 2);

    xg_gemm64<<<GRID_M, 256>>>(pA, cWih + 3*GG*HH, cbih + 3*GG);
    gru_rec64<<<128, 256>>>(pXG, cWhh + 3*GG*HH, cbhh + 3*GG, out, hid, 2, 3);

    // prices passthrough
    tail_kernel<<<1, 512>>>(prices, pr);
}

// round 13
// speedup vs baseline: 1.5860x; 1.0144x over previous
#include <cuda_runtime.h>
#include <cstdint>

// Problem dims
#define NS   512                 // B*S
#define DD   150
#define HH   64
#define GG   192                 // 3H
#define LTT  32
#define LCC  128
#define LSEQ 160                 // LTT + LCC
#define ROWS_T (NS*LTT)          // 16384
#define ROWS_ALL (NS*(LTT+LCC))  // 81920

// Scratch (device globals; no runtime alloc allowed)
__device__ float g_X [ROWS_ALL*DD];   // embed sums (layer0 input)
__device__ float g_xg[ROWS_ALL*GG];   // per-layer input projection, plain [row][gate]
__device__ float g_A [ROWS_ALL*HH];
__device__ float g_B [ROWS_ALL*HH];

// ---------- f32x2 helpers ----------
__device__ __forceinline__ unsigned long long pk2(float a, float b){
    unsigned long long r; asm("mov.b64 %0,{%1,%2};" : "=l"(r) : "f"(a), "f"(b)); return r;
}
__device__ __forceinline__ void fma2(unsigned long long &acc, unsigned long long a, unsigned long long b){
    asm("fma.rn.f32x2 %0, %1, %2, %0;" : "+l"(acc) : "l"(a), "l"(b));
}
__device__ __forceinline__ float upk_sum(unsigned long long a){
    float x, y; asm("mov.b64 {%0,%1}, %2;" : "=f"(x), "=f"(y) : "l"(a)); return x + y;
}
__device__ __forceinline__ float sigmoidf_(float x){
    return __fdividef(1.f, 1.f + __expf(-x));
}
__device__ __forceinline__ float tanhf_(float x){
    float ax = fabsf(x);
    float e  = __expf(-2.f*ax);
    float t  = __fdividef(1.f - e, 1.f + e);
    return (x < 0.f) ? -t : t;
}

// ---------- 1) embedding-bag sums ----------
__global__ void embed_kernel(const int* __restrict__ titles,
                             const int* __restrict__ contents,
                             const float* __restrict__ emb)
{
    int idx = blockIdx.x*blockDim.x + threadIdx.x;
    if (idx >= ROWS_ALL*75) return;          // 75 float2 per row (D=150)
    int row = idx / 75;
    int dp  = idx - row*75;

    const int* ip; int stride;
    if (row < ROWS_T){ int n = row >> 5, t = row & 31;  ip = titles   + (n*6)*32  + t; stride = 32; }
    else             { int r = row - ROWS_T;
                       int n = r >> 7,   t = r & 127;   ip = contents + (n*6)*128 + t; stride = 128; }

    float ax = 0.f, ay = 0.f;
    #pragma unroll
    for (int i = 0; i < 6; i++){
        int ix = ip[i*stride];
        if (ix != 0){
            float2 v = *(const float2*)(emb + (size_t)ix*DD + 2*dp);
            ax += v.x; ay += v.y;
        }
    }
    *(float2*)(g_X + (size_t)row*DD + 2*dp) = make_float2(ax, ay);
}

// ---------- 2a) layer-0 input projection GEMM (K=150), fp32, plain store ----------
__global__ void __launch_bounds__(256, 3) xg_gemm150(const float* __restrict__ W,
                                                     const float* __restrict__ bias)
{
    __shared__ float  sw [30*194];
    __shared__ float2 sxd[64*31];
    int tid = threadIdx.x;
    int tx = tid & 31, ty = tid >> 5;
    int r0 = blockIdx.x * 64;

    unsigned long long acc[8][3];
    #pragma unroll
    for (int r = 0; r < 8; r++)
        #pragma unroll
        for (int c = 0; c < 3; c++) acc[r][c] = 0ull;

    for (int k0 = 0; k0 < 150; k0 += 30){
        for (int i = tid; i < 30*192; i += 256){
            int gg = i/30, kk = i - gg*30;
            sw[kk*194 + gg] = W[gg*150 + k0 + kk];
        }
        for (int i = tid; i < 64*30; i += 256){
            int rr = i/30, kk = i - rr*30;
            float v = g_X[(size_t)(r0+rr)*150 + k0 + kk];
            sxd[rr*31 + kk] = make_float2(v, v);
        }
        __syncthreads();
        #pragma unroll 6
        for (int kk = 0; kk < 30; kk++){
            unsigned long long w2[3];
            #pragma unroll
            for (int c = 0; c < 3; c++)
                w2[c] = *(const unsigned long long*)&sw[kk*194 + tx*6 + 2*c];
            #pragma unroll
            for (int r = 0; r < 8; r++){
                unsigned long long x2 = *(const unsigned long long*)&sxd[(ty*8 + r)*31 + kk];
                #pragma unroll
                for (int c = 0; c < 3; c++) fma2(acc[r][c], w2[c], x2);
            }
        }
        __syncthreads();
    }
    #pragma unroll
    for (int r = 0; r < 8; r++){
        int row = r0 + ty*8 + r;
        #pragma unroll
        for (int c = 0; c < 3; c++){
            float lo, hi;
            asm("mov.b64 {%0,%1}, %2;" : "=f"(lo), "=f"(hi) : "l"(acc[r][c]));
            int g0 = tx*6 + 2*c;
            float2 o; o.x = lo + bias[g0]; o.y = hi + bias[g0+1];
            *(float2*)(g_xg + (size_t)row*GG + g0) = o;
        }
    }
}

// ---------- 2b) K=64 projection GEMM, k-paired f32x2, no duplication ----------
// Tile 64 rows x 96 cols (half of GG). Grid = (ROWS_ALL/64)*2.
// Single smem fill (full K=64), ONE barrier, 16 fully-unrolled 4-k blocks.
#define SWP 68   // padded row stride (floats): 272B, 16B-aligned, LDS.128 conflict-free
__global__ void __launch_bounds__(256, 3) xg_gemm64(const float* __restrict__ X,
                                                    const float* __restrict__ W,
                                                    const float* __restrict__ bias)
{
    __shared__ float sw[96*SWP];
    __shared__ float sx[64*SWP];
    const int tid = threadIdx.x;
    const int tx = tid & 31, ty = tid >> 5;
    const int r0 = (blockIdx.x >> 1) * 64;
    const int c0 = (blockIdx.x & 1) * 96;

    for (int i = tid; i < 96*16; i += 256){
        int g = i >> 4, kq = i & 15;
        float4 v = *(const float4*)(W + (size_t)(c0 + g)*64 + kq*4);
        *(float4*)(sw + g*SWP + kq*4) = v;
    }
    for (int i = tid; i < 64*16; i += 256){
        int r = i >> 4, kq = i & 15;
        float4 v = *(const float4*)(X + (size_t)(r0 + r)*64 + kq*4);
        *(float4*)(sx + r*SWP + kq*4) = v;
    }
    __syncthreads();

    unsigned long long acc[8][3];
    #pragma unroll
    for (int r = 0; r < 8; r++)
        #pragma unroll
        for (int c = 0; c < 3; c++) acc[r][c] = 0ull;

    #pragma unroll
    for (int k4 = 0; k4 < 16; k4++){
        ulonglong2 wv[3];
        #pragma unroll
        for (int c = 0; c < 3; c++)
            wv[c] = *(const ulonglong2*)(sw + (tx + 32*c)*SWP + k4*4);
        #pragma unroll
        for (int r = 0; r < 8; r++){
            ulonglong2 xv = *(const ulonglong2*)(sx + (ty*8 + r)*SWP + k4*4);
            #pragma unroll
            for (int c = 0; c < 3; c++){
                fma2(acc[r][c], wv[c].x, xv.x);
                fma2(acc[r][c], wv[c].y, xv.y);
            }
        }
    }

    #pragma unroll
    for (int r = 0; r < 8; r++){
        int row = r0 + ty*8 + r;
        #pragma unroll
        for (int c = 0; c < 3; c++){
            int col = c0 + tx + 32*c;
            g_xg[(size_t)row*GG + col] = upk_sum(acc[r][c]) + __ldg(bias + col);
        }
    }
}

// ---------- 3) GRU recurrence: 64-thread groups, occ-2 CTAs ----------
// Block 128 = 2 groups of 64 threads; grid 256 (512 groups, one wave on 148 SMs,
// 2 CTAs/SM co-resident -> 4 warps/SMSP from independent barrier domains).
// Thread k owns gate rows k (r), 64+k (z), 128+k (n): all gates + h-update
// computed locally. One named barrier (id=grp, 64 thr) per step; h double-
// buffered in shared. Accumulators split into 2 chains each (depth 16).
// mode 0: info mid (X layout out), mode 1: info final (concat out), mode 2: comb.
__global__ void __launch_bounds__(128, 2) gru_rec64(
    const float* __restrict__ xg,
    const float* __restrict__ Whh, const float* __restrict__ bhh,
    float* __restrict__ yout, float* __restrict__ hid,
    int mode, int layer)
{
    __shared__ __align__(16) float sh_h[2][2][64];

    const int tid = threadIdx.x;
    const int grp = tid >> 6, k = tid & 63;
    const int gid = blockIdx.x*2 + grp;        // 0..511

    // weight rows r,z,n -> registers (3 x 32 f32x2)
    unsigned long long wr[32], wz[32], wn[32];
    {
        const float2* pr_ = (const float2*)(Whh + (size_t)k*HH);
        const float2* pz_ = (const float2*)(Whh + (size_t)(64 + k)*HH);
        const float2* pn_ = (const float2*)(Whh + (size_t)(128 + k)*HH);
        #pragma unroll
        for (int j = 0; j < 32; j++){
            float2 a = __ldg(pr_ + j); wr[j] = pk2(a.x, a.y);
            float2 b = __ldg(pz_ + j); wz[j] = pk2(b.x, b.y);
            float2 c = __ldg(pn_ + j); wn[j] = pk2(c.x, c.y);
        }
    }
    const float br_ = bhh[k], bz_ = bhh[64 + k], bn_ = bhh[128 + k];

    const int NSEG = (mode == 2) ? 1 : 2;
    float hk = 0.f;

    for (int seg = 0; seg < NSEG; seg++){
        int T, ibase, ob;
        if (mode == 2){        ibase = gid*LSEQ;            T = LSEQ; ob = ibase; }
        else if (seg == 0){    ibase = ROWS_T + gid*LCC;    T = LCC;
                               ob = (mode == 1) ? gid*LSEQ + LTT : ibase; }
        else {                 ibase = gid*LTT;             T = LTT;
                               ob = (mode == 1) ? gid*LSEQ : ibase; }

        hk = 0.f;
        sh_h[grp][0][k] = 0.f;

        int xoff = ibase*GG + k;
        float axr = __ldg(xg + xoff);
        float axz = __ldg(xg + xoff + 64);
        float axn = __ldg(xg + xoff + 128);
        asm volatile("bar.sync %0, %1;" :: "r"(grp), "r"(64) : "memory");

        int p = 0;
        for (int t = 0; t < T; t++){
            // prefetch next step's xg
            float nxr = 0.f, nxz = 0.f, nxn = 0.f;
            if (t+1 < T){
                int xo = (ibase + t + 1)*GG + k;
                nxr = __ldg(xg + xo);
                nxz = __ldg(xg + xo + 64);
                nxn = __ldg(xg + xo + 128);
            }

            // three matvecs, 2 chains each (depth 16)
            unsigned long long ar0 = 0ull, ar1 = 0ull;
            unsigned long long az0 = 0ull, az1 = 0ull;
            unsigned long long an0 = 0ull, an1 = 0ull;
            const ulonglong2* hp = (const ulonglong2*)sh_h[grp][p];
            #pragma unroll
            for (int j = 0; j < 16; j++){
                ulonglong2 h4 = hp[j];
                fma2(ar0, wr[2*j],   h4.x);  fma2(ar1, wr[2*j+1], h4.y);
                fma2(az0, wz[2*j],   h4.x);  fma2(az1, wz[2*j+1], h4.y);
                fma2(an0, wn[2*j],   h4.x);  fma2(an1, wn[2*j+1], h4.y);
            }

            float gr = sigmoidf_(axr + br_ + upk_sum(ar0) + upk_sum(ar1));
            float gz = sigmoidf_(axz + bz_ + upk_sum(az0) + upk_sum(az1));
            float gn = tanhf_(axn + gr*(bn_ + upk_sum(an0) + upk_sum(an1)));
            hk = gz*(hk - gn) + gn;

            sh_h[grp][p^1][k] = hk;
            yout[(size_t)(ob + t)*HH + k] = hk;

            asm volatile("bar.sync %0, %1;" :: "r"(grp), "r"(64) : "memory");
            axr = nxr; axz = nxz; axn = nxn;
            p ^= 1;
        }
    }

    if (mode == 2 && hid != nullptr){
        int bi = gid >> 6, sidx = gid & 63;
        hid[(size_t)(((bi*4 + layer)*64 + sidx)*64) + k] = hk;
    }
}

// ---------- 4) prices passthrough ----------
__global__ void tail_kernel(const float* __restrict__ prices, float* __restrict__ out){
    int i = threadIdx.x;
    if (i < 512) out[i] = prices[i];
}

extern "C" void kernel_launch(void* const* d_in, const int* in_sizes, int n_in,
                              void* d_out, int out_size)
{
    const int*   titles   = (const int*)  d_in[0];
    const int*   contents = (const int*)  d_in[1];
    const float* prices   = (const float*)d_in[2];
    const float* emb      = (const float*)d_in[3];
    const float* iWih0    = (const float*)d_in[4];
    const float* iWhh0    = (const float*)d_in[5];
    const float* ibih0    = (const float*)d_in[6];
    const float* ibhh0    = (const float*)d_in[7];
    const float* iWih     = (const float*)d_in[8];   // [3][192][64]
    const float* iWhh     = (const float*)d_in[9];
    const float* ibih     = (const float*)d_in[10];  // [3][192]
    const float* ibhh     = (const float*)d_in[11];
    const float* cWih     = (const float*)d_in[12];  // [4][192][64]
    const float* cWhh     = (const float*)d_in[13];
    const float* cbih     = (const float*)d_in[14];
    const float* cbhh     = (const float*)d_in[15];

    float* out = (float*)d_out;
    float* hid = out + (size_t)8*64*160*64;          // encoder_hidden region
    float* pr  = hid + (size_t)8*4*64*64;            // prices region

    float *pXG = nullptr, *pA = nullptr, *pB = nullptr;
    cudaGetSymbolAddress((void**)&pXG, g_xg);
    cudaGetSymbolAddress((void**)&pA,  g_A);
    cudaGetSymbolAddress((void**)&pB,  g_B);

    const int GRID_M = (ROWS_ALL/64)*2;   // 2560 (row-tile x col-half)
    const int GRID_R = 256;               // rec: 512 groups / 2 per CTA

    // 1) embedding bags
    embed_kernel<<<(ROWS_ALL*75 + 255)/256, 256>>>(titles, contents, emb);

    // info layer 0
    xg_gemm150<<<ROWS_ALL/64, 256>>>(iWih0, ibih0);
    gru_rec64<<<GRID_R, 128>>>(pXG, iWhh0, ibhh0, pA, nullptr, 0, 0);

    // info layers 1..3; layer 3 writes concat layout
    xg_gemm64<<<GRID_M, 256>>>(pA, iWih + 0*GG*HH, ibih + 0*GG);
    gru_rec64<<<GRID_R, 128>>>(pXG, iWhh + 0*GG*HH, ibhh + 0*GG, pB, nullptr, 0, 0);

    xg_gemm64<<<GRID_M, 256>>>(pB, iWih + 1*GG*HH, ibih + 1*GG);
    gru_rec64<<<GRID_R, 128>>>(pXG, iWhh + 1*GG*HH, ibhh + 1*GG, pA, nullptr, 0, 0);

    xg_gemm64<<<GRID_M, 256>>>(pA, iWih + 2*GG*HH, ibih + 2*GG);
    gru_rec64<<<GRID_R, 128>>>(pXG, iWhh + 2*GG*HH, ibhh + 2*GG, pB, nullptr, 1, 0);

    // comb layers 0..3 (concat layout, T=160); final layer writes encoder_outputs
    xg_gemm64<<<GRID_M, 256>>>(pB, cWih + 0*GG*HH, cbih + 0*GG);
    gru_rec64<<<GRID_R, 128>>>(pXG, cWhh + 0*GG*HH, cbhh + 0*GG, pA,  hid, 2, 0);

    xg_gemm64<<<GRID_M, 256>>>(pA, cWih + 1*GG*HH, cbih + 1*GG);
    gru_rec64<<<GRID_R, 128>>>(pXG, cWhh + 1*GG*HH, cbhh + 1*GG, pB,  hid, 2, 1);

    xg_gemm64<<<GRID_M, 256>>>(pB, cWih + 2*GG*HH, cbih + 2*GG);
    gru_rec64<<<GRID_R, 128>>>(pXG, cWhh + 2*GG*HH, cbhh + 2*GG, pA,  hid, 2, 2);

    xg_gemm64<<<GRID_M, 256>>>(pA, cWih + 3*GG*HH, cbih + 3*GG);
    gru_rec64<<<GRID_R, 128>>>(pXG, cWhh + 3*GG*HH, cbhh + 3*GG, out, hid, 2, 3);

    // prices passthrough
    tail_kernel<<<1, 512>>>(prices, pr);
}